// round 10
// baseline (speedup 1.0000x reference)
#include <cuda_runtime.h>
#include <math.h>

#define B_ 4
#define N_ 10000
#define E_ 160000
#define F_ 64
#define D_ 128
#define H_ 4

// ---------------- scratch (static device globals; no allocation) ------------
__device__ float g_h0[B_ * N_ * D_];
__device__ float g_h1[B_ * N_ * D_];
__device__ float g_gbuf[B_ * N_ * D_];
__device__ float g_es[B_ * N_ * H_];
__device__ float g_ed[B_ * N_ * H_];
__device__ int   g_deg[B_ * N_];
__device__ int   g_rowptr[B_ * (N_ + 1)];
__device__ int   g_fill[B_ * N_];
__device__ int   g_csr[B_ * E_];
__device__ float g_gacc[B_ * D_];
__device__ float g_msum[B_];

// ---------------- zero init (deterministic per launch) ----------------------
__global__ void zero_kernel() {
    int i = blockIdx.x * blockDim.x + threadIdx.x;
    if (i < B_ * N_) g_deg[i] = 0;
    if (i < B_ * D_) g_gacc[i] = 0.f;
    if (i < B_) g_msum[i] = 0.f;
}

// ---------------- CSR build: count -> scan -> scatter -----------------------
__global__ void count_kernel(const int* __restrict__ ei) {
    int i = blockIdx.x * blockDim.x + threadIdx.x;
    if (i >= B_ * E_) return;
    int b = i / E_, e = i - b * E_;
    int dst = ei[b * 2 * E_ + E_ + e];
    atomicAdd(&g_deg[b * N_ + dst], 1);
}

__global__ void scan_kernel() {
    int b = blockIdx.x;
    __shared__ int s[256];
    __shared__ int carry;
    if (threadIdx.x == 0) carry = 0;
    __syncthreads();
    for (int base = 0; base < N_; base += 256) {
        int i = base + threadIdx.x;
        int v = (i < N_) ? g_deg[b * N_ + i] : 0;
        s[threadIdx.x] = v;
        __syncthreads();
        for (int off = 1; off < 256; off <<= 1) {
            int t = (threadIdx.x >= off) ? s[threadIdx.x - off] : 0;
            __syncthreads();
            s[threadIdx.x] += t;
            __syncthreads();
        }
        int excl = s[threadIdx.x] - v;
        if (i < N_) {
            int p = carry + excl;
            g_rowptr[b * (N_ + 1) + i] = p;
            g_fill[b * N_ + i] = p;
        }
        __syncthreads();
        if (threadIdx.x == 255) carry += s[255];
        __syncthreads();
    }
    if (threadIdx.x == 0) g_rowptr[b * (N_ + 1) + N_] = carry;
}

__global__ void scatter_kernel(const int* __restrict__ ei) {
    int i = blockIdx.x * blockDim.x + threadIdx.x;
    if (i >= B_ * E_) return;
    int b = i / E_, e = i - b * E_;
    int src = ei[b * 2 * E_ + e];
    int dst = ei[b * 2 * E_ + E_ + e];
    int pos = atomicAdd(&g_fill[b * N_ + dst], 1);
    g_csr[(size_t)b * E_ + pos] = src;
}

// ---------------- SGEMM: C[M,128] = A[M,K] @ W[K,128] + bias (+type embed) --
// BM=64, BN=128, BK=16, 256 threads, TM=4, TN=8
__global__ __launch_bounds__(256, 2) void gemm_kernel(
    const float* __restrict__ A, const float* __restrict__ W,
    const float* __restrict__ bias, float* __restrict__ C,
    int M, int K,
    const int* __restrict__ types, const float* __restrict__ tembed)
{
    __shared__ float As[16][64];
    __shared__ float Ws[16][128];
    const int tid = threadIdx.x;
    const int tr = tid >> 4;          // 0..15 -> rows tr*4..
    const int tc = tid & 15;          // 0..15 -> cols tc*8..
    const int row0 = blockIdx.x * 64;
    const int arow = tid >> 2;        // 0..63
    const int ac4 = (tid & 3) * 4;    // 0,4,8,12

    float acc[4][8];
#pragma unroll
    for (int i = 0; i < 4; i++)
#pragma unroll
        for (int j = 0; j < 8; j++) acc[i][j] = 0.f;

    for (int k0 = 0; k0 < K; k0 += 16) {
        float4 av = make_float4(0.f, 0.f, 0.f, 0.f);
        int grow = row0 + arow;
        if (grow < M) av = *(const float4*)(A + (size_t)grow * K + k0 + ac4);
        As[ac4 + 0][arow] = av.x;
        As[ac4 + 1][arow] = av.y;
        As[ac4 + 2][arow] = av.z;
        As[ac4 + 3][arow] = av.w;
#pragma unroll
        for (int it = 0; it < 2; it++) {
            int idx = tid + it * 256;        // 0..511
            int wr = idx >> 5;               // 0..15
            int wc = (idx & 31) * 4;         // 0..124
            *(float4*)(&Ws[wr][wc]) =
                *(const float4*)(W + (size_t)(k0 + wr) * 128 + wc);
        }
        __syncthreads();
#pragma unroll
        for (int k = 0; k < 16; k++) {
            float4 a = *(const float4*)(&As[k][tr * 4]);
            float4 b0 = *(const float4*)(&Ws[k][tc * 8]);
            float4 b1 = *(const float4*)(&Ws[k][tc * 8 + 4]);
            float aa[4] = {a.x, a.y, a.z, a.w};
            float bb[8] = {b0.x, b0.y, b0.z, b0.w, b1.x, b1.y, b1.z, b1.w};
#pragma unroll
            for (int i = 0; i < 4; i++)
#pragma unroll
                for (int j = 0; j < 8; j++) acc[i][j] += aa[i] * bb[j];
        }
        __syncthreads();
    }
    float4 bias0 = *(const float4*)(bias + tc * 8);
    float4 bias1 = *(const float4*)(bias + tc * 8 + 4);
#pragma unroll
    for (int i = 0; i < 4; i++) {
        int grow = row0 + tr * 4 + i;
        if (grow >= M) continue;
        float4 o0 = make_float4(acc[i][0] + bias0.x, acc[i][1] + bias0.y,
                                acc[i][2] + bias0.z, acc[i][3] + bias0.w);
        float4 o1 = make_float4(acc[i][4] + bias1.x, acc[i][5] + bias1.y,
                                acc[i][6] + bias1.z, acc[i][7] + bias1.w);
        if (types) {
            const float* te = tembed + (size_t)types[grow] * 128;
            float4 t0 = *(const float4*)(te + tc * 8);
            float4 t1 = *(const float4*)(te + tc * 8 + 4);
            o0.x += t0.x; o0.y += t0.y; o0.z += t0.z; o0.w += t0.w;
            o1.x += t1.x; o1.y += t1.y; o1.z += t1.z; o1.w += t1.w;
        }
        *(float4*)(C + (size_t)grow * 128 + tc * 8) = o0;
        *(float4*)(C + (size_t)grow * 128 + tc * 8 + 4) = o1;
    }
}

// ---------------- e_s / e_d per node: one warp per node ---------------------
__global__ void esed_kernel(const float* __restrict__ g,
                            const float* __restrict__ a_s,
                            const float* __restrict__ a_d) {
    int wid = (blockIdx.x * blockDim.x + threadIdx.x) >> 5;
    int lane = threadIdx.x & 31;
    if (wid >= B_ * N_) return;
    int head = lane >> 3;
    int kk = (lane & 7) * 4;
    float4 gv = *(const float4*)(g + (size_t)wid * D_ + lane * 4);
    float4 as = *(const float4*)(a_s + head * 32 + kk);
    float4 ad = *(const float4*)(a_d + head * 32 + kk);
    float ps = gv.x * as.x + gv.y * as.y + gv.z * as.z + gv.w * as.w;
    float pd = gv.x * ad.x + gv.y * ad.y + gv.z * ad.z + gv.w * ad.w;
#pragma unroll
    for (int off = 1; off < 8; off <<= 1) {
        ps += __shfl_xor_sync(0xffffffffu, ps, off);
        pd += __shfl_xor_sync(0xffffffffu, pd, off);
    }
    if ((lane & 7) == 0) {
        g_es[wid * H_ + head] = ps;
        g_ed[wid * H_ + head] = pd;
    }
}

// ---------------- GAT aggregation: warp/node, online softmax, no atomics ----
__global__ __launch_bounds__(256) void agg_kernel(const float* __restrict__ g,
                                                  const float* __restrict__ h_in,
                                                  const float* __restrict__ mask,
                                                  float* __restrict__ h_out) {
    int wid = (blockIdx.x * blockDim.x + threadIdx.x) >> 5;
    int lane = threadIdx.x & 31;
    if (wid >= B_ * N_) return;
    int b = wid / N_, n = wid - b * N_;
    const int* rp = g_rowptr + b * (N_ + 1);
    const int* cs = g_csr + (size_t)b * E_;
    const float* gb = g + (size_t)b * N_ * D_;
    const float* esb = g_es + (size_t)b * N_ * H_;
    int head = lane >> 3;
    float edh = g_ed[(size_t)wid * H_ + head];
    float m = -1e30f, d = 0.f;
    float4 acc = make_float4(0.f, 0.f, 0.f, 0.f);
    int s0 = rp[n], s1 = rp[n + 1];
    for (int p = s0; p < s1; p++) {
        int src = cs[p];
        float e = esb[src * H_ + head] + edh;
        e = e > 0.f ? e : 0.2f * e;          // leaky_relu(0.2)
        float mn = fmaxf(m, e);
        float sc = __expf(m - mn);
        float pw = __expf(e - mn);
        d = d * sc + pw;
        float4 gv = *(const float4*)(gb + (size_t)src * D_ + lane * 4);
        acc.x = acc.x * sc + pw * gv.x;
        acc.y = acc.y * sc + pw * gv.y;
        acc.z = acc.z * sc + pw * gv.z;
        acc.w = acc.w * sc + pw * gv.w;
        m = mn;
    }
    float inv = 1.f / (d + 1e-16f);
    float mk = mask[b * N_ + n];
    float4 hv = *(const float4*)(h_in + (size_t)wid * D_ + lane * 4);
    float4 o;
    float v;
    v = acc.x * inv + hv.x; o.x = (v > 0.f ? v : expm1f(v)) * mk;
    v = acc.y * inv + hv.y; o.y = (v > 0.f ? v : expm1f(v)) * mk;
    v = acc.z * inv + hv.z; o.z = (v > 0.f ? v : expm1f(v)) * mk;
    v = acc.w * inv + hv.w; o.w = (v > 0.f ? v : expm1f(v)) * mk;
    *(float4*)(h_out + (size_t)wid * D_ + lane * 4) = o;
}

// ---------------- graph embedding -------------------------------------------
__global__ void graph_accum_kernel(const float* __restrict__ node_emb,
                                   const float* __restrict__ mask) {
    int b = blockIdx.y;
    int o = threadIdx.x;          // 128
    int n0 = blockIdx.x * 250;
    int n1 = n0 + 250;
    float s = 0.f;
    for (int n = n0; n < n1; n++) {
        float mk = mask[b * N_ + n];
        s += node_emb[((size_t)(b * N_ + n)) * D_ + o] * mk;
    }
    atomicAdd(&g_gacc[b * D_ + o], s);
}

__global__ void msum_kernel(const float* __restrict__ mask) {
    int b = threadIdx.x >> 5;
    int lane = threadIdx.x & 31;
    if (b >= B_) return;
    float s = 0.f;
    for (int n = lane; n < N_; n += 32) s += mask[b * N_ + n];
#pragma unroll
    for (int off = 16; off > 0; off >>= 1) s += __shfl_xor_sync(0xffffffffu, s, off);
    if (lane == 0) g_msum[b] = s;
}

__global__ void finalize_kernel(float* __restrict__ out) {
    int i = blockIdx.x * blockDim.x + threadIdx.x;
    if (i >= B_ * D_) return;
    int b = i / D_;
    float ms = g_msum[b];
    ms = ms < 1.f ? 1.f : ms;
    out[(size_t)B_ * N_ * D_ + i] = g_gacc[i] / ms;
}

// ---------------- launch -----------------------------------------------------
static float* symf(const void* s) { void* p = nullptr; cudaGetSymbolAddress(&p, s); return (float*)p; }

extern "C" void kernel_launch(void* const* d_in, const int* in_sizes, int n_in,
                              void* d_out, int out_size) {
    const float* node_features = (const float*)d_in[0];
    const int*   edge_index    = (const int*)d_in[1];
    const int*   node_types    = (const int*)d_in[2];
    const float* node_mask     = (const float*)d_in[3];
    const float* type_embed    = (const float*)d_in[4];
    const float* in_W          = (const float*)d_in[5];
    const float* in_b          = (const float*)d_in[6];
    const float* gat_W         = (const float*)d_in[7];
    const float* gat_b         = (const float*)d_in[8];
    const float* a_src         = (const float*)d_in[9];
    const float* a_dst         = (const float*)d_in[10];
    const float* out_W         = (const float*)d_in[11];
    const float* out_b         = (const float*)d_in[12];
    float* out = (float*)d_out;

    float* h0   = symf(g_h0);
    float* h1   = symf(g_h1);
    float* gbuf = symf(g_gbuf);

    const int M = B_ * N_;

    // init + CSR build (dst is layer-invariant -> build once, reuse twice)
    zero_kernel<<<(B_ * N_ + 255) / 256, 256>>>();
    count_kernel<<<(B_ * E_ + 255) / 256, 256>>>(edge_index);
    scan_kernel<<<B_, 256>>>();
    scatter_kernel<<<(B_ * E_ + 255) / 256, 256>>>(edge_index);

    // input projection + type embedding
    gemm_kernel<<<(M + 63) / 64, 256>>>(node_features, in_W, in_b, h0,
                                        M, F_, node_types, type_embed);

    const int warps_grid = (B_ * N_ * 32 + 255) / 256;

    // layer 0
    gemm_kernel<<<(M + 63) / 64, 256>>>(h0, gat_W, gat_b, gbuf, M, D_,
                                        nullptr, nullptr);
    esed_kernel<<<warps_grid, 256>>>(gbuf, a_src, a_dst);
    agg_kernel<<<warps_grid, 256>>>(gbuf, h0, node_mask, h1);

    // layer 1
    gemm_kernel<<<(M + 63) / 64, 256>>>(h1, gat_W + D_ * D_, gat_b + D_, gbuf,
                                        M, D_, nullptr, nullptr);
    esed_kernel<<<warps_grid, 256>>>(gbuf, a_src + H_ * (D_ / H_),
                                     a_dst + H_ * (D_ / H_));
    agg_kernel<<<warps_grid, 256>>>(gbuf, h1, node_mask, h0);

    // output projection -> node_emb (directly into d_out)
    gemm_kernel<<<(M + 63) / 64, 256>>>(h0, out_W, out_b, out, M, D_,
                                        nullptr, nullptr);

    // graph embedding
    dim3 gg(40, B_);
    graph_accum_kernel<<<gg, 128>>>(out, node_mask);
    msum_kernel<<<1, 128>>>(node_mask);
    finalize_kernel<<<2, 256>>>(out);
}

// round 12
// speedup vs baseline: 1.0638x; 1.0638x over previous
#include <cuda_runtime.h>
#include <math.h>

#define B_ 4
#define N_ 10000
#define E_ 160000
#define F_ 64
#define D_ 128
#define H_ 4

// ---------------- scratch (static device globals; no allocation) ------------
__device__ float g_h0[B_ * N_ * D_];
__device__ float g_h1[B_ * N_ * D_];
__device__ float g_gbuf[B_ * N_ * D_];
__device__ float g_es[B_ * N_ * H_];
__device__ float g_ed[B_ * N_ * H_];
__device__ int   g_deg[B_ * N_];
__device__ int   g_rowptr[B_ * (N_ + 1)];
__device__ int   g_fill[B_ * N_];
__device__ int   g_csr[B_ * E_];
__device__ float g_gacc[B_ * D_];
__device__ float g_msum[B_];

// ---------------- zero init (deterministic per launch) ----------------------
__global__ void zero_kernel() {
    int i = blockIdx.x * blockDim.x + threadIdx.x;
    if (i < B_ * N_) g_deg[i] = 0;
    if (i < B_ * D_) g_gacc[i] = 0.f;
    if (i < B_) g_msum[i] = 0.f;
}

// ---------------- CSR build: count -> scan -> scatter -----------------------
__global__ void count_kernel(const int* __restrict__ ei) {
    int i = blockIdx.x * blockDim.x + threadIdx.x;
    if (i >= B_ * E_) return;
    int b = i / E_, e = i - b * E_;
    int dst = ei[b * 2 * E_ + E_ + e];
    atomicAdd(&g_deg[b * N_ + dst], 1);
}

__global__ void scan_kernel() {
    int b = blockIdx.x;
    __shared__ int s[256];
    __shared__ int carry;
    if (threadIdx.x == 0) carry = 0;
    __syncthreads();
    for (int base = 0; base < N_; base += 256) {
        int i = base + threadIdx.x;
        int v = (i < N_) ? g_deg[b * N_ + i] : 0;
        s[threadIdx.x] = v;
        __syncthreads();
        for (int off = 1; off < 256; off <<= 1) {
            int t = (threadIdx.x >= off) ? s[threadIdx.x - off] : 0;
            __syncthreads();
            s[threadIdx.x] += t;
            __syncthreads();
        }
        int excl = s[threadIdx.x] - v;
        if (i < N_) {
            int p = carry + excl;
            g_rowptr[b * (N_ + 1) + i] = p;
            g_fill[b * N_ + i] = p;
        }
        __syncthreads();
        if (threadIdx.x == 255) carry += s[255];
        __syncthreads();
    }
    if (threadIdx.x == 0) g_rowptr[b * (N_ + 1) + N_] = carry;
}

__global__ void scatter_kernel(const int* __restrict__ ei) {
    int i = blockIdx.x * blockDim.x + threadIdx.x;
    if (i >= B_ * E_) return;
    int b = i / E_, e = i - b * E_;
    int src = ei[b * 2 * E_ + e];
    int dst = ei[b * 2 * E_ + E_ + e];
    int pos = atomicAdd(&g_fill[b * N_ + dst], 1);
    g_csr[(size_t)b * E_ + pos] = src;
}

// ---------------- SGEMM: C[M,128] = A[M,K] @ W[K,128] + bias (+type embed) --
// BM=128, BN=128, BK=16, 256 threads, TM=8, TN=8, double-buffered smem,
// register-staged gmem prefetch, one __syncthreads per k-tile.
__global__ __launch_bounds__(256, 1) void gemm_kernel(
    const float* __restrict__ A, const float* __restrict__ W,
    const float* __restrict__ bias, float* __restrict__ C,
    int M, int K,
    const int* __restrict__ types, const float* __restrict__ tembed)
{
    __shared__ float As[2][16][128];   // [buf][k][row]  (A transposed)
    __shared__ float Ws[2][16][128];   // [buf][k][col]
    const int tid = threadIdx.x;
    const int tr = tid >> 4;           // 0..15 -> rows tr*8..
    const int tc = tid & 15;           // 0..15 -> cols tc*8..
    const int row0 = blockIdx.x * 128;
    const int KT = K >> 4;

    float acc[8][8];
#pragma unroll
    for (int i = 0; i < 8; i++)
#pragma unroll
        for (int j = 0; j < 8; j++) acc[i][j] = 0.f;

    float4 avr[2], wvr[2];

    // prologue: load tile 0 -> smem buf 0
    {
#pragma unroll
        for (int it = 0; it < 2; it++) {
            int idx = tid + it * 256;          // 0..511
            int ar = idx >> 2, c4 = (idx & 3) * 4;
            int grow = row0 + ar;
            float4 av = make_float4(0.f, 0.f, 0.f, 0.f);
            if (grow < M) av = *(const float4*)(A + (size_t)grow * K + c4);
            As[0][c4 + 0][ar] = av.x;
            As[0][c4 + 1][ar] = av.y;
            As[0][c4 + 2][ar] = av.z;
            As[0][c4 + 3][ar] = av.w;
            int wr = idx >> 5, wc = (idx & 31) * 4;
            *(float4*)(&Ws[0][wr][wc]) =
                *(const float4*)(W + (size_t)wr * 128 + wc);
        }
    }
    __syncthreads();

    for (int kt = 0; kt < KT; kt++) {
        // prefetch next tile into registers
        if (kt + 1 < KT) {
            int k0 = (kt + 1) << 4;
#pragma unroll
            for (int it = 0; it < 2; it++) {
                int idx = tid + it * 256;
                int ar = idx >> 2, c4 = (idx & 3) * 4;
                int grow = row0 + ar;
                avr[it] = make_float4(0.f, 0.f, 0.f, 0.f);
                if (grow < M)
                    avr[it] = *(const float4*)(A + (size_t)grow * K + k0 + c4);
                int wr = idx >> 5, wc = (idx & 31) * 4;
                wvr[it] = *(const float4*)(W + (size_t)(k0 + wr) * 128 + wc);
            }
        }
        // compute current tile
        {
            const float (*as)[128] = As[kt & 1];
            const float (*ws)[128] = Ws[kt & 1];
#pragma unroll
            for (int k = 0; k < 16; k++) {
                float4 a0 = *(const float4*)(&as[k][tr * 8]);
                float4 a1 = *(const float4*)(&as[k][tr * 8 + 4]);
                float4 b0 = *(const float4*)(&ws[k][tc * 8]);
                float4 b1 = *(const float4*)(&ws[k][tc * 8 + 4]);
                float aa[8] = {a0.x, a0.y, a0.z, a0.w, a1.x, a1.y, a1.z, a1.w};
                float bb[8] = {b0.x, b0.y, b0.z, b0.w, b1.x, b1.y, b1.z, b1.w};
#pragma unroll
                for (int i = 0; i < 8; i++)
#pragma unroll
                    for (int j = 0; j < 8; j++) acc[i][j] += aa[i] * bb[j];
            }
        }
        // store prefetched tile into the idle buffer.
        // Safe without a pre-sync: the idle buffer's last readers finished
        // before the barrier at the end of the previous iteration.
        if (kt + 1 < KT) {
            int nb = (kt + 1) & 1;
#pragma unroll
            for (int it = 0; it < 2; it++) {
                int idx = tid + it * 256;
                int ar = idx >> 2, c4 = (idx & 3) * 4;
                As[nb][c4 + 0][ar] = avr[it].x;
                As[nb][c4 + 1][ar] = avr[it].y;
                As[nb][c4 + 2][ar] = avr[it].z;
                As[nb][c4 + 3][ar] = avr[it].w;
                int wr = idx >> 5, wc = (idx & 31) * 4;
                *(float4*)(&Ws[nb][wr][wc]) = wvr[it];
            }
            __syncthreads();
        }
    }

    float4 bias0 = *(const float4*)(bias + tc * 8);
    float4 bias1 = *(const float4*)(bias + tc * 8 + 4);
#pragma unroll
    for (int i = 0; i < 8; i++) {
        int grow = row0 + tr * 8 + i;
        if (grow >= M) continue;
        float4 o0 = make_float4(acc[i][0] + bias0.x, acc[i][1] + bias0.y,
                                acc[i][2] + bias0.z, acc[i][3] + bias0.w);
        float4 o1 = make_float4(acc[i][4] + bias1.x, acc[i][5] + bias1.y,
                                acc[i][6] + bias1.z, acc[i][7] + bias1.w);
        if (types) {
            const float* te = tembed + (size_t)types[grow] * 128;
            float4 t0 = *(const float4*)(te + tc * 8);
            float4 t1 = *(const float4*)(te + tc * 8 + 4);
            o0.x += t0.x; o0.y += t0.y; o0.z += t0.z; o0.w += t0.w;
            o1.x += t1.x; o1.y += t1.y; o1.z += t1.z; o1.w += t1.w;
        }
        *(float4*)(C + (size_t)grow * 128 + tc * 8) = o0;
        *(float4*)(C + (size_t)grow * 128 + tc * 8 + 4) = o1;
    }
}

// ---------------- e_s / e_d per node: one warp per node ---------------------
__global__ void esed_kernel(const float* __restrict__ g,
                            const float* __restrict__ a_s,
                            const float* __restrict__ a_d) {
    int wid = (blockIdx.x * blockDim.x + threadIdx.x) >> 5;
    int lane = threadIdx.x & 31;
    if (wid >= B_ * N_) return;
    int head = lane >> 3;
    int kk = (lane & 7) * 4;
    float4 gv = *(const float4*)(g + (size_t)wid * D_ + lane * 4);
    float4 as = *(const float4*)(a_s + head * 32 + kk);
    float4 ad = *(const float4*)(a_d + head * 32 + kk);
    float ps = gv.x * as.x + gv.y * as.y + gv.z * as.z + gv.w * as.w;
    float pd = gv.x * ad.x + gv.y * ad.y + gv.z * ad.z + gv.w * ad.w;
#pragma unroll
    for (int off = 1; off < 8; off <<= 1) {
        ps += __shfl_xor_sync(0xffffffffu, ps, off);
        pd += __shfl_xor_sync(0xffffffffu, pd, off);
    }
    if ((lane & 7) == 0) {
        g_es[wid * H_ + head] = ps;
        g_ed[wid * H_ + head] = pd;
    }
}

// ---------------- GAT aggregation: warp/node, online softmax, no atomics ----
__global__ __launch_bounds__(256) void agg_kernel(const float* __restrict__ g,
                                                  const float* __restrict__ h_in,
                                                  const float* __restrict__ mask,
                                                  float* __restrict__ h_out) {
    int wid = (blockIdx.x * blockDim.x + threadIdx.x) >> 5;
    int lane = threadIdx.x & 31;
    if (wid >= B_ * N_) return;
    int b = wid / N_, n = wid - b * N_;
    const int* rp = g_rowptr + b * (N_ + 1);
    const int* cs = g_csr + (size_t)b * E_;
    const float* gb = g + (size_t)b * N_ * D_;
    const float* esb = g_es + (size_t)b * N_ * H_;
    int head = lane >> 3;
    float edh = g_ed[(size_t)wid * H_ + head];
    float m = -1e30f, d = 0.f;
    float4 acc = make_float4(0.f, 0.f, 0.f, 0.f);
    int s0 = rp[n], s1 = rp[n + 1];
    for (int p = s0; p < s1; p++) {
        int src = cs[p];
        float e = esb[src * H_ + head] + edh;
        e = e > 0.f ? e : 0.2f * e;          // leaky_relu(0.2)
        float mn = fmaxf(m, e);
        float sc = __expf(m - mn);
        float pw = __expf(e - mn);
        d = d * sc + pw;
        float4 gv = *(const float4*)(gb + (size_t)src * D_ + lane * 4);
        acc.x = acc.x * sc + pw * gv.x;
        acc.y = acc.y * sc + pw * gv.y;
        acc.z = acc.z * sc + pw * gv.z;
        acc.w = acc.w * sc + pw * gv.w;
        m = mn;
    }
    float inv = 1.f / (d + 1e-16f);
    float mk = mask[b * N_ + n];
    float4 hv = *(const float4*)(h_in + (size_t)wid * D_ + lane * 4);
    float4 o;
    float v;
    v = acc.x * inv + hv.x; o.x = (v > 0.f ? v : expm1f(v)) * mk;
    v = acc.y * inv + hv.y; o.y = (v > 0.f ? v : expm1f(v)) * mk;
    v = acc.z * inv + hv.z; o.z = (v > 0.f ? v : expm1f(v)) * mk;
    v = acc.w * inv + hv.w; o.w = (v > 0.f ? v : expm1f(v)) * mk;
    *(float4*)(h_out + (size_t)wid * D_ + lane * 4) = o;
}

// ---------------- graph embedding -------------------------------------------
__global__ void graph_accum_kernel(const float* __restrict__ node_emb,
                                   const float* __restrict__ mask) {
    int b = blockIdx.y;
    int o = threadIdx.x;          // 128
    int n0 = blockIdx.x * 250;
    int n1 = n0 + 250;
    float s = 0.f;
    for (int n = n0; n < n1; n++) {
        float mk = mask[b * N_ + n];
        s += node_emb[((size_t)(b * N_ + n)) * D_ + o] * mk;
    }
    atomicAdd(&g_gacc[b * D_ + o], s);
}

__global__ void msum_kernel(const float* __restrict__ mask) {
    int b = threadIdx.x >> 5;
    int lane = threadIdx.x & 31;
    if (b >= B_) return;
    float s = 0.f;
    for (int n = lane; n < N_; n += 32) s += mask[b * N_ + n];
#pragma unroll
    for (int off = 16; off > 0; off >>= 1) s += __shfl_xor_sync(0xffffffffu, s, off);
    if (lane == 0) g_msum[b] = s;
}

__global__ void finalize_kernel(float* __restrict__ out) {
    int i = blockIdx.x * blockDim.x + threadIdx.x;
    if (i >= B_ * D_) return;
    int b = i / D_;
    float ms = g_msum[b];
    ms = ms < 1.f ? 1.f : ms;
    out[(size_t)B_ * N_ * D_ + i] = g_gacc[i] / ms;
}

// ---------------- launch -----------------------------------------------------
static float* symf(const void* s) { void* p = nullptr; cudaGetSymbolAddress(&p, s); return (float*)p; }

extern "C" void kernel_launch(void* const* d_in, const int* in_sizes, int n_in,
                              void* d_out, int out_size) {
    const float* node_features = (const float*)d_in[0];
    const int*   edge_index    = (const int*)d_in[1];
    const int*   node_types    = (const int*)d_in[2];
    const float* node_mask     = (const float*)d_in[3];
    const float* type_embed    = (const float*)d_in[4];
    const float* in_W          = (const float*)d_in[5];
    const float* in_b          = (const float*)d_in[6];
    const float* gat_W         = (const float*)d_in[7];
    const float* gat_b         = (const float*)d_in[8];
    const float* a_src         = (const float*)d_in[9];
    const float* a_dst         = (const float*)d_in[10];
    const float* out_W         = (const float*)d_in[11];
    const float* out_b         = (const float*)d_in[12];
    float* out = (float*)d_out;

    float* h0   = symf(g_h0);
    float* h1   = symf(g_h1);
    float* gbuf = symf(g_gbuf);

    const int M = B_ * N_;
    const int gemm_grid = (M + 127) / 128;

    // init + CSR build (dst is layer-invariant -> build once, reuse twice)
    zero_kernel<<<(B_ * N_ + 255) / 256, 256>>>();
    count_kernel<<<(B_ * E_ + 255) / 256, 256>>>(edge_index);
    scan_kernel<<<B_, 256>>>();
    scatter_kernel<<<(B_ * E_ + 255) / 256, 256>>>(edge_index);

    // input projection + type embedding
    gemm_kernel<<<gemm_grid, 256>>>(node_features, in_W, in_b, h0,
                                    M, F_, node_types, type_embed);

    const int warps_grid = (B_ * N_ * 32 + 255) / 256;

    // layer 0
    gemm_kernel<<<gemm_grid, 256>>>(h0, gat_W, gat_b, gbuf, M, D_,
                                    nullptr, nullptr);
    esed_kernel<<<warps_grid, 256>>>(gbuf, a_src, a_dst);
    agg_kernel<<<warps_grid, 256>>>(gbuf, h0, node_mask, h1);

    // layer 1
    gemm_kernel<<<gemm_grid, 256>>>(h1, gat_W + D_ * D_, gat_b + D_, gbuf,
                                    M, D_, nullptr, nullptr);
    esed_kernel<<<warps_grid, 256>>>(gbuf, a_src + H_ * (D_ / H_),
                                     a_dst + H_ * (D_ / H_));
    agg_kernel<<<warps_grid, 256>>>(gbuf, h1, node_mask, h0);

    // output projection -> node_emb (directly into d_out)
    gemm_kernel<<<gemm_grid, 256>>>(h0, out_W, out_b, out, M, D_,
                                    nullptr, nullptr);

    // graph embedding
    dim3 gg(40, B_);
    graph_accum_kernel<<<gg, 128>>>(out, node_mask);
    msum_kernel<<<1, 128>>>(node_mask);
    finalize_kernel<<<2, 256>>>(out);
}

// round 13
// speedup vs baseline: 1.5547x; 1.4615x over previous
#include <cuda_runtime.h>
#include <math.h>

#define B_ 4
#define N_ 10000
#define E_ 160000
#define F_ 64
#define D_ 128
#define H_ 4

// ---------------- scratch (static device globals; no allocation) ------------
__device__ float g_h0[B_ * N_ * D_];
__device__ float g_h1[B_ * N_ * D_];
__device__ float g_gbuf[B_ * N_ * D_];
__device__ float g_es[B_ * N_ * H_];
__device__ float g_ed[B_ * N_ * H_];
__device__ int   g_deg[B_ * N_];
__device__ int   g_rowptr[B_ * (N_ + 1)];
__device__ int   g_fill[B_ * N_];
__device__ int   g_csr[B_ * E_];
__device__ float g_gacc[B_ * D_];
__device__ float g_msum[B_];

// ---------------- zero init (deterministic per launch) ----------------------
__global__ void zero_kernel() {
    int i = blockIdx.x * blockDim.x + threadIdx.x;
    if (i < B_ * N_) g_deg[i] = 0;
    if (i < B_ * D_) g_gacc[i] = 0.f;
    if (i < B_) g_msum[i] = 0.f;
}

// ---------------- CSR build: count -> scan -> scatter -----------------------
__global__ void count_kernel(const int* __restrict__ ei) {
    int i = blockIdx.x * blockDim.x + threadIdx.x;
    if (i >= B_ * E_) return;
    int b = i / E_, e = i - b * E_;
    int dst = ei[b * 2 * E_ + E_ + e];
    atomicAdd(&g_deg[b * N_ + dst], 1);
}

__global__ void scan_kernel() {
    int b = blockIdx.x;
    __shared__ int s[256];
    __shared__ int carry;
    if (threadIdx.x == 0) carry = 0;
    __syncthreads();
    for (int base = 0; base < N_; base += 256) {
        int i = base + threadIdx.x;
        int v = (i < N_) ? g_deg[b * N_ + i] : 0;
        s[threadIdx.x] = v;
        __syncthreads();
        for (int off = 1; off < 256; off <<= 1) {
            int t = (threadIdx.x >= off) ? s[threadIdx.x - off] : 0;
            __syncthreads();
            s[threadIdx.x] += t;
            __syncthreads();
        }
        int excl = s[threadIdx.x] - v;
        if (i < N_) {
            int p = carry + excl;
            g_rowptr[b * (N_ + 1) + i] = p;
            g_fill[b * N_ + i] = p;
        }
        __syncthreads();
        if (threadIdx.x == 255) carry += s[255];
        __syncthreads();
    }
    if (threadIdx.x == 0) g_rowptr[b * (N_ + 1) + N_] = carry;
}

__global__ void scatter_kernel(const int* __restrict__ ei) {
    int i = blockIdx.x * blockDim.x + threadIdx.x;
    if (i >= B_ * E_) return;
    int b = i / E_, e = i - b * E_;
    int src = ei[b * 2 * E_ + e];
    int dst = ei[b * 2 * E_ + E_ + e];
    int pos = atomicAdd(&g_fill[b * N_ + dst], 1);
    g_csr[(size_t)b * E_ + pos] = src;
}

// ---------------- tf32 tensor-core GEMM --------------------------------------
// C[M,128] = A[M,K] @ W[K,128] + bias (+ optional type embed)
// One CTA = 128 rows. Whole A-tile (128xK) and W (Kx128) staged in smem once,
// converted to tf32 at store time. 8 warps (4x2), warp tile 32x64,
// mma.sync.m16n8k8.row.col.f32.tf32.tf32.f32.
__device__ __forceinline__ unsigned f2tf(float x) {
    unsigned u;
    asm("cvt.rna.tf32.f32 %0, %1;" : "=r"(u) : "f"(x));
    return u;
}

template <int K>
__global__ __launch_bounds__(256, 1) void gemm_tc(
    const float* __restrict__ A, const float* __restrict__ W,
    const float* __restrict__ bias, float* __restrict__ C, int M,
    const int* __restrict__ types, const float* __restrict__ tembed)
{
    constexpr int KP = K + 4;      // A row pad: a-frag banks 4g+q -> distinct
    constexpr int NP = 136;        // W row pad: b-frag banks 8q+g -> distinct
    extern __shared__ unsigned smem[];
    unsigned* As = smem;                 // [128][KP]
    unsigned* Ws = smem + 128 * KP;      // [K][NP]

    const int tid = threadIdx.x;
    const int lane = tid & 31;
    const int warp = tid >> 5;
    const int mblk = (warp >> 1) * 32;
    const int nblk = (warp & 1) * 64;
    const int row0 = blockIdx.x * 128;
    const int g4 = lane >> 2;       // groupID 0..7
    const int q4 = lane & 3;        // threadID-in-group 0..3

    // ---- stage A (convert to tf32) ----
    constexpr int K4 = K / 4;
#pragma unroll
    for (int it = 0; it < (128 * K4) / 256; it++) {
        int idx = tid + it * 256;
        int r = idx / K4, c4 = (idx % K4) * 4;
        float4 v = make_float4(0.f, 0.f, 0.f, 0.f);
        if (row0 + r < M) v = *(const float4*)(A + (size_t)(row0 + r) * K + c4);
        uint4 u;
        u.x = f2tf(v.x); u.y = f2tf(v.y); u.z = f2tf(v.z); u.w = f2tf(v.w);
        *(uint4*)(As + r * KP + c4) = u;
    }
    // ---- stage W (convert to tf32) ----
#pragma unroll
    for (int it = 0; it < (K * 32) / 256; it++) {
        int idx = tid + it * 256;
        int r = idx >> 5, c4 = (idx & 31) * 4;
        float4 v = *(const float4*)(W + (size_t)r * 128 + c4);
        uint4 u;
        u.x = f2tf(v.x); u.y = f2tf(v.y); u.z = f2tf(v.z); u.w = f2tf(v.w);
        *(uint4*)(Ws + r * NP + c4) = u;
    }
    __syncthreads();

    float acc[2][8][4];
#pragma unroll
    for (int mt = 0; mt < 2; mt++)
#pragma unroll
        for (int nt = 0; nt < 8; nt++)
#pragma unroll
            for (int c = 0; c < 4; c++) acc[mt][nt][c] = 0.f;

#pragma unroll 4
    for (int k0 = 0; k0 < K; k0 += 8) {
        unsigned a[2][4];
#pragma unroll
        for (int mt = 0; mt < 2; mt++) {
            int r = mblk + mt * 16 + g4;
            int c = k0 + q4;
            a[mt][0] = As[r * KP + c];
            a[mt][1] = As[(r + 8) * KP + c];
            a[mt][2] = As[r * KP + c + 4];
            a[mt][3] = As[(r + 8) * KP + c + 4];
        }
#pragma unroll
        for (int nt = 0; nt < 8; nt++) {
            int n = nblk + nt * 8 + g4;
            unsigned b0 = Ws[(k0 + q4) * NP + n];
            unsigned b1 = Ws[(k0 + 4 + q4) * NP + n];
#pragma unroll
            for (int mt = 0; mt < 2; mt++) {
                float* cc = acc[mt][nt];
                asm volatile(
                    "mma.sync.aligned.m16n8k8.row.col.f32.tf32.tf32.f32 "
                    "{%0,%1,%2,%3}, {%4,%5,%6,%7}, {%8,%9}, {%0,%1,%2,%3};"
                    : "+f"(cc[0]), "+f"(cc[1]), "+f"(cc[2]), "+f"(cc[3])
                    : "r"(a[mt][0]), "r"(a[mt][1]), "r"(a[mt][2]), "r"(a[mt][3]),
                      "r"(b0), "r"(b1));
            }
        }
    }

    // ---- epilogue: bias (+type embed), write C ----
#pragma unroll
    for (int mt = 0; mt < 2; mt++) {
        int rt = row0 + mblk + mt * 16 + g4;
        int rb = rt + 8;
        const float* tet = nullptr;
        const float* teb = nullptr;
        if (types) {
            if (rt < M) tet = tembed + (size_t)types[rt] * 128;
            if (rb < M) teb = tembed + (size_t)types[rb] * 128;
        }
#pragma unroll
        for (int nt = 0; nt < 8; nt++) {
            int cbase = nblk + nt * 8 + q4 * 2;
            float b0 = bias[cbase], b1 = bias[cbase + 1];
            if (rt < M) {
                float o0 = acc[mt][nt][0] + b0;
                float o1 = acc[mt][nt][1] + b1;
                if (tet) { o0 += tet[cbase]; o1 += tet[cbase + 1]; }
                *(float2*)(C + (size_t)rt * 128 + cbase) = make_float2(o0, o1);
            }
            if (rb < M) {
                float o2 = acc[mt][nt][2] + b0;
                float o3 = acc[mt][nt][3] + b1;
                if (teb) { o2 += teb[cbase]; o3 += teb[cbase + 1]; }
                *(float2*)(C + (size_t)rb * 128 + cbase) = make_float2(o2, o3);
            }
        }
    }
}

// ---------------- e_s / e_d per node: one warp per node ---------------------
__global__ void esed_kernel(const float* __restrict__ g,
                            const float* __restrict__ a_s,
                            const float* __restrict__ a_d) {
    int wid = (blockIdx.x * blockDim.x + threadIdx.x) >> 5;
    int lane = threadIdx.x & 31;
    if (wid >= B_ * N_) return;
    int head = lane >> 3;
    int kk = (lane & 7) * 4;
    float4 gv = *(const float4*)(g + (size_t)wid * D_ + lane * 4);
    float4 as = *(const float4*)(a_s + head * 32 + kk);
    float4 ad = *(const float4*)(a_d + head * 32 + kk);
    float ps = gv.x * as.x + gv.y * as.y + gv.z * as.z + gv.w * as.w;
    float pd = gv.x * ad.x + gv.y * ad.y + gv.z * ad.z + gv.w * ad.w;
#pragma unroll
    for (int off = 1; off < 8; off <<= 1) {
        ps += __shfl_xor_sync(0xffffffffu, ps, off);
        pd += __shfl_xor_sync(0xffffffffu, pd, off);
    }
    if ((lane & 7) == 0) {
        g_es[wid * H_ + head] = ps;
        g_ed[wid * H_ + head] = pd;
    }
}

// ---------------- GAT aggregation: warp/node, online softmax, no atomics ----
__global__ __launch_bounds__(256) void agg_kernel(const float* __restrict__ g,
                                                  const float* __restrict__ h_in,
                                                  const float* __restrict__ mask,
                                                  float* __restrict__ h_out) {
    int wid = (blockIdx.x * blockDim.x + threadIdx.x) >> 5;
    int lane = threadIdx.x & 31;
    if (wid >= B_ * N_) return;
    int b = wid / N_, n = wid - b * N_;
    const int* rp = g_rowptr + b * (N_ + 1);
    const int* cs = g_csr + (size_t)b * E_;
    const float* gb = g + (size_t)b * N_ * D_;
    const float* esb = g_es + (size_t)b * N_ * H_;
    int head = lane >> 3;
    float edh = g_ed[(size_t)wid * H_ + head];
    float m = -1e30f, d = 0.f;
    float4 acc = make_float4(0.f, 0.f, 0.f, 0.f);
    int s0 = rp[n], s1 = rp[n + 1];
    for (int p = s0; p < s1; p++) {
        int src = cs[p];
        float e = esb[src * H_ + head] + edh;
        e = e > 0.f ? e : 0.2f * e;          // leaky_relu(0.2)
        float mn = fmaxf(m, e);
        float sc = __expf(m - mn);
        float pw = __expf(e - mn);
        d = d * sc + pw;
        float4 gv = *(const float4*)(gb + (size_t)src * D_ + lane * 4);
        acc.x = acc.x * sc + pw * gv.x;
        acc.y = acc.y * sc + pw * gv.y;
        acc.z = acc.z * sc + pw * gv.z;
        acc.w = acc.w * sc + pw * gv.w;
        m = mn;
    }
    float inv = 1.f / (d + 1e-16f);
    float mk = mask[b * N_ + n];
    float4 hv = *(const float4*)(h_in + (size_t)wid * D_ + lane * 4);
    float4 o;
    float v;
    v = acc.x * inv + hv.x; o.x = (v > 0.f ? v : expm1f(v)) * mk;
    v = acc.y * inv + hv.y; o.y = (v > 0.f ? v : expm1f(v)) * mk;
    v = acc.z * inv + hv.z; o.z = (v > 0.f ? v : expm1f(v)) * mk;
    v = acc.w * inv + hv.w; o.w = (v > 0.f ? v : expm1f(v)) * mk;
    *(float4*)(h_out + (size_t)wid * D_ + lane * 4) = o;
}

// ---------------- graph embedding -------------------------------------------
__global__ void graph_accum_kernel(const float* __restrict__ node_emb,
                                   const float* __restrict__ mask) {
    int b = blockIdx.y;
    int o = threadIdx.x;          // 128
    int n0 = blockIdx.x * 250;
    int n1 = n0 + 250;
    float s = 0.f;
    for (int n = n0; n < n1; n++) {
        float mk = mask[b * N_ + n];
        s += node_emb[((size_t)(b * N_ + n)) * D_ + o] * mk;
    }
    atomicAdd(&g_gacc[b * D_ + o], s);
}

__global__ void msum_kernel(const float* __restrict__ mask) {
    int b = threadIdx.x >> 5;
    int lane = threadIdx.x & 31;
    if (b >= B_) return;
    float s = 0.f;
    for (int n = lane; n < N_; n += 32) s += mask[b * N_ + n];
#pragma unroll
    for (int off = 16; off > 0; off >>= 1) s += __shfl_xor_sync(0xffffffffu, s, off);
    if (lane == 0) g_msum[b] = s;
}

__global__ void finalize_kernel(float* __restrict__ out) {
    int i = blockIdx.x * blockDim.x + threadIdx.x;
    if (i >= B_ * D_) return;
    int b = i / D_;
    float ms = g_msum[b];
    ms = ms < 1.f ? 1.f : ms;
    out[(size_t)B_ * N_ * D_ + i] = g_gacc[i] / ms;
}

// ---------------- launch -----------------------------------------------------
static float* symf(const void* s) { void* p = nullptr; cudaGetSymbolAddress(&p, s); return (float*)p; }

extern "C" void kernel_launch(void* const* d_in, const int* in_sizes, int n_in,
                              void* d_out, int out_size) {
    const float* node_features = (const float*)d_in[0];
    const int*   edge_index    = (const int*)d_in[1];
    const int*   node_types    = (const int*)d_in[2];
    const float* node_mask     = (const float*)d_in[3];
    const float* type_embed    = (const float*)d_in[4];
    const float* in_W          = (const float*)d_in[5];
    const float* in_b          = (const float*)d_in[6];
    const float* gat_W         = (const float*)d_in[7];
    const float* gat_b         = (const float*)d_in[8];
    const float* a_src         = (const float*)d_in[9];
    const float* a_dst         = (const float*)d_in[10];
    const float* out_W         = (const float*)d_in[11];
    const float* out_b         = (const float*)d_in[12];
    float* out = (float*)d_out;

    float* h0   = symf(g_h0);
    float* h1   = symf(g_h1);
    float* gbuf = symf(g_gbuf);

    const int M = B_ * N_;
    const int gemm_grid = (M + 127) / 128;

    // dynamic smem: A[128][K+4] + W[K][136] (tf32 words)
    const int SMEM64  = (128 * (64 + 4)  + 64  * 136) * 4;   // 69,632
    const int SMEM128 = (128 * (128 + 4) + 128 * 136) * 4;   // 137,216
    cudaFuncSetAttribute(gemm_tc<64>,
                         cudaFuncAttributeMaxDynamicSharedMemorySize, SMEM64);
    cudaFuncSetAttribute(gemm_tc<128>,
                         cudaFuncAttributeMaxDynamicSharedMemorySize, SMEM128);

    // init + CSR build (dst is layer-invariant -> build once, reuse twice)
    zero_kernel<<<(B_ * N_ + 255) / 256, 256>>>();
    count_kernel<<<(B_ * E_ + 255) / 256, 256>>>(edge_index);
    scan_kernel<<<B_, 256>>>();
    scatter_kernel<<<(B_ * E_ + 255) / 256, 256>>>(edge_index);

    // input projection + type embedding
    gemm_tc<64><<<gemm_grid, 256, SMEM64>>>(node_features, in_W, in_b, h0,
                                            M, node_types, type_embed);

    const int warps_grid = (B_ * N_ * 32 + 255) / 256;

    // layer 0
    gemm_tc<128><<<gemm_grid, 256, SMEM128>>>(h0, gat_W, gat_b, gbuf, M,
                                              nullptr, nullptr);
    esed_kernel<<<warps_grid, 256>>>(gbuf, a_src, a_dst);
    agg_kernel<<<warps_grid, 256>>>(gbuf, h0, node_mask, h1);

    // layer 1
    gemm_tc<128><<<gemm_grid, 256, SMEM128>>>(h1, gat_W + D_ * D_, gat_b + D_,
                                              gbuf, M, nullptr, nullptr);
    esed_kernel<<<warps_grid, 256>>>(gbuf, a_src + H_ * (D_ / H_),
                                     a_dst + H_ * (D_ / H_));
    agg_kernel<<<warps_grid, 256>>>(gbuf, h1, node_mask, h0);

    // output projection -> node_emb (directly into d_out)
    gemm_tc<128><<<gemm_grid, 256, SMEM128>>>(h0, out_W, out_b, out, M,
                                              nullptr, nullptr);

    // graph embedding
    dim3 gg(40, B_);
    graph_accum_kernel<<<gg, 128>>>(out, node_mask);
    msum_kernel<<<1, 128>>>(node_mask);
    finalize_kernel<<<2, 256>>>(out);
}

// round 14
// speedup vs baseline: 1.7765x; 1.1426x over previous
#include <cuda_runtime.h>
#include <math.h>

#define B_ 4
#define N_ 10000
#define E_ 160000
#define F_ 64
#define D_ 128
#define H_ 4

// ---------------- scratch (static device globals; no allocation) ------------
__device__ float g_h0[B_ * N_ * D_];
__device__ float g_h1[B_ * N_ * D_];
__device__ float g_gbuf[B_ * N_ * D_];
__device__ float g_es[B_ * N_ * H_];
__device__ float g_ed[B_ * N_ * H_];
__device__ int   g_deg[B_ * N_];
__device__ int   g_rowptr[B_ * (N_ + 1)];
__device__ int   g_fill[B_ * N_];
__device__ int   g_csr[B_ * E_];
__device__ float g_gacc[B_ * D_];
__device__ float g_msum[B_];

// ---------------- zero init (deterministic per launch) ----------------------
__global__ void zero_kernel() {
    int i = blockIdx.x * blockDim.x + threadIdx.x;
    if (i < B_ * N_) g_deg[i] = 0;
    if (i < B_ * D_) g_gacc[i] = 0.f;
    if (i < B_) g_msum[i] = 0.f;
}

// ---------------- CSR build: count -> scan -> scatter -----------------------
__global__ void count_kernel(const int* __restrict__ ei) {
    int i = blockIdx.x * blockDim.x + threadIdx.x;
    if (i >= B_ * E_) return;
    int b = i / E_, e = i - b * E_;
    int dst = ei[b * 2 * E_ + E_ + e];
    atomicAdd(&g_deg[b * N_ + dst], 1);
}

// warp-shuffle scan, 1024 threads per batch, 10 chunks
__global__ __launch_bounds__(1024) void scan_kernel() {
    int b = blockIdx.x;
    int tid = threadIdx.x, lane = tid & 31, wid = tid >> 5;
    __shared__ int wsum[32];
    __shared__ int s_carry, s_tot;
    if (tid == 0) s_carry = 0;
    __syncthreads();
    for (int base = 0; base < N_; base += 1024) {
        int i = base + tid;
        int v = (i < N_) ? g_deg[b * N_ + i] : 0;
        int inc = v;
#pragma unroll
        for (int o = 1; o < 32; o <<= 1) {
            int t = __shfl_up_sync(0xffffffffu, inc, o);
            if (lane >= o) inc += t;
        }
        if (lane == 31) wsum[wid] = inc;
        __syncthreads();
        if (wid == 0) {
            int sv = wsum[lane];
            int si = sv;
#pragma unroll
            for (int o = 1; o < 32; o <<= 1) {
                int t = __shfl_up_sync(0xffffffffu, si, o);
                if (lane >= o) si += t;
            }
            wsum[lane] = si - sv;
            if (lane == 31) s_tot = si;
        }
        __syncthreads();
        int excl = s_carry + wsum[wid] + inc - v;
        if (i < N_) {
            g_rowptr[b * (N_ + 1) + i] = excl;
            g_fill[b * N_ + i] = excl;
        }
        __syncthreads();
        if (tid == 0) s_carry += s_tot;
        __syncthreads();
    }
    if (tid == 0) g_rowptr[b * (N_ + 1) + N_] = s_carry;
}

__global__ void scatter_kernel(const int* __restrict__ ei) {
    int i = blockIdx.x * blockDim.x + threadIdx.x;
    if (i >= B_ * E_) return;
    int b = i / E_, e = i - b * E_;
    int src = ei[b * 2 * E_ + e];
    int dst = ei[b * 2 * E_ + E_ + e];
    int pos = atomicAdd(&g_fill[b * N_ + dst], 1);
    g_csr[(size_t)b * E_ + pos] = src;
}

// ---------------- tf32 tensor-core GEMM (+ fused e_s/e_d epilogue) ----------
// C[M,128] = A[M,K] @ W[K,128] + bias (+ optional type embed)
// If aS != null: also writes g_es/g_ed[row,head] = sum_k C[row,head*32+k]*a[k]
__device__ __forceinline__ unsigned f2tf(float x) {
    unsigned u;
    asm("cvt.rna.tf32.f32 %0, %1;" : "=r"(u) : "f"(x));
    return u;
}

template <int K>
__global__ __launch_bounds__(256, 1) void gemm_tc(
    const float* __restrict__ A, const float* __restrict__ W,
    const float* __restrict__ bias, float* __restrict__ C, int M,
    const int* __restrict__ types, const float* __restrict__ tembed,
    const float* __restrict__ aS, const float* __restrict__ aD)
{
    constexpr int KP = K + 4;
    constexpr int NP = 136;
    extern __shared__ unsigned smem[];
    unsigned* As = smem;                 // [128][KP]
    unsigned* Ws = smem + 128 * KP;      // [K][NP]

    const int tid = threadIdx.x;
    const int lane = tid & 31;
    const int warp = tid >> 5;
    const int mblk = (warp >> 1) * 32;
    const int nblk = (warp & 1) * 64;
    const int row0 = blockIdx.x * 128;
    const int g4 = lane >> 2;
    const int q4 = lane & 3;

    constexpr int K4 = K / 4;
#pragma unroll
    for (int it = 0; it < (128 * K4) / 256; it++) {
        int idx = tid + it * 256;
        int r = idx / K4, c4 = (idx % K4) * 4;
        float4 v = make_float4(0.f, 0.f, 0.f, 0.f);
        if (row0 + r < M) v = *(const float4*)(A + (size_t)(row0 + r) * K + c4);
        uint4 u;
        u.x = f2tf(v.x); u.y = f2tf(v.y); u.z = f2tf(v.z); u.w = f2tf(v.w);
        *(uint4*)(As + r * KP + c4) = u;
    }
#pragma unroll
    for (int it = 0; it < (K * 32) / 256; it++) {
        int idx = tid + it * 256;
        int r = idx >> 5, c4 = (idx & 31) * 4;
        float4 v = *(const float4*)(W + (size_t)r * 128 + c4);
        uint4 u;
        u.x = f2tf(v.x); u.y = f2tf(v.y); u.z = f2tf(v.z); u.w = f2tf(v.w);
        *(uint4*)(Ws + r * NP + c4) = u;
    }
    __syncthreads();

    float acc[2][8][4];
#pragma unroll
    for (int mt = 0; mt < 2; mt++)
#pragma unroll
        for (int nt = 0; nt < 8; nt++)
#pragma unroll
            for (int c = 0; c < 4; c++) acc[mt][nt][c] = 0.f;

#pragma unroll 4
    for (int k0 = 0; k0 < K; k0 += 8) {
        unsigned a[2][4];
#pragma unroll
        for (int mt = 0; mt < 2; mt++) {
            int r = mblk + mt * 16 + g4;
            int c = k0 + q4;
            a[mt][0] = As[r * KP + c];
            a[mt][1] = As[(r + 8) * KP + c];
            a[mt][2] = As[r * KP + c + 4];
            a[mt][3] = As[(r + 8) * KP + c + 4];
        }
#pragma unroll
        for (int nt = 0; nt < 8; nt++) {
            int n = nblk + nt * 8 + g4;
            unsigned b0 = Ws[(k0 + q4) * NP + n];
            unsigned b1 = Ws[(k0 + 4 + q4) * NP + n];
#pragma unroll
            for (int mt = 0; mt < 2; mt++) {
                float* cc = acc[mt][nt];
                asm volatile(
                    "mma.sync.aligned.m16n8k8.row.col.f32.tf32.tf32.f32 "
                    "{%0,%1,%2,%3}, {%4,%5,%6,%7}, {%8,%9}, {%0,%1,%2,%3};"
                    : "+f"(cc[0]), "+f"(cc[1]), "+f"(cc[2]), "+f"(cc[3])
                    : "r"(a[mt][0]), "r"(a[mt][1]), "r"(a[mt][2]), "r"(a[mt][3]),
                      "r"(b0), "r"(b1));
            }
        }
    }

    const int hb0 = nblk >> 5;   // head base for this warp: 0 or 2
#pragma unroll
    for (int mt = 0; mt < 2; mt++) {
        int rt = row0 + mblk + mt * 16 + g4;
        int rb = rt + 8;
        const float* tet = nullptr;
        const float* teb = nullptr;
        if (types) {
            if (rt < M) tet = tembed + (size_t)types[rt] * 128;
            if (rb < M) teb = tembed + (size_t)types[rb] * 128;
        }
        float es_t[2] = {0.f, 0.f}, ed_t[2] = {0.f, 0.f};
        float es_b[2] = {0.f, 0.f}, ed_b[2] = {0.f, 0.f};
#pragma unroll
        for (int nt = 0; nt < 8; nt++) {
            int cbase = nblk + nt * 8 + q4 * 2;
            float b0 = bias[cbase], b1 = bias[cbase + 1];
            float o0 = acc[mt][nt][0] + b0;
            float o1 = acc[mt][nt][1] + b1;
            float o2 = acc[mt][nt][2] + b0;
            float o3 = acc[mt][nt][3] + b1;
            if (tet) { o0 += tet[cbase]; o1 += tet[cbase + 1]; }
            if (teb) { o2 += teb[cbase]; o3 += teb[cbase + 1]; }
            if (rt < M) *(float2*)(C + (size_t)rt * 128 + cbase) = make_float2(o0, o1);
            if (rb < M) *(float2*)(C + (size_t)rb * 128 + cbase) = make_float2(o2, o3);
            if (aS) {
                int h = nt >> 2;                     // head within warp (0/1)
                int cw = (nt & 3) * 8 + q4 * 2;      // col within head
                int hg = (hb0 + h) * 32 + cw;
                float as0 = aS[hg], as1 = aS[hg + 1];
                float ad0 = aD[hg], ad1 = aD[hg + 1];
                es_t[h] += o0 * as0 + o1 * as1;
                ed_t[h] += o0 * ad0 + o1 * ad1;
                es_b[h] += o2 * as0 + o3 * as1;
                ed_b[h] += o2 * ad0 + o3 * ad1;
            }
        }
        if (aS) {
            // quad reduce (lanes g4*4+q4, q4=0..3)
#pragma unroll
            for (int h = 0; h < 2; h++) {
                es_t[h] += __shfl_xor_sync(0xffffffffu, es_t[h], 1);
                es_t[h] += __shfl_xor_sync(0xffffffffu, es_t[h], 2);
                ed_t[h] += __shfl_xor_sync(0xffffffffu, ed_t[h], 1);
                ed_t[h] += __shfl_xor_sync(0xffffffffu, ed_t[h], 2);
                es_b[h] += __shfl_xor_sync(0xffffffffu, es_b[h], 1);
                es_b[h] += __shfl_xor_sync(0xffffffffu, es_b[h], 2);
                ed_b[h] += __shfl_xor_sync(0xffffffffu, ed_b[h], 1);
                ed_b[h] += __shfl_xor_sync(0xffffffffu, ed_b[h], 2);
            }
            if (q4 == 0) {
                if (rt < M) {
                    *(float2*)(g_es + (size_t)rt * H_ + hb0) = make_float2(es_t[0], es_t[1]);
                    *(float2*)(g_ed + (size_t)rt * H_ + hb0) = make_float2(ed_t[0], ed_t[1]);
                }
                if (rb < M) {
                    *(float2*)(g_es + (size_t)rb * H_ + hb0) = make_float2(es_b[0], es_b[1]);
                    *(float2*)(g_ed + (size_t)rb * H_ + hb0) = make_float2(ed_b[0], ed_b[1]);
                }
            }
        }
    }
}

// ---------------- GAT aggregation: warp/node, two-pass softmax, no atomics --
// Pass 1: exact segment max (matches reference). Pass 2: exp+accumulate with
// no loop-carried dependency except pure adds -> high MLP.
__global__ __launch_bounds__(256) void agg_kernel(const float* __restrict__ g,
                                                  const float* __restrict__ h_in,
                                                  const float* __restrict__ mask,
                                                  float* __restrict__ h_out) {
    int wid = (blockIdx.x * blockDim.x + threadIdx.x) >> 5;
    int lane = threadIdx.x & 31;
    if (wid >= B_ * N_) return;
    int b = wid / N_, n = wid - b * N_;
    const int* rp = g_rowptr + b * (N_ + 1);
    const int* cs = g_csr + (size_t)b * E_;
    const float* gb = g + (size_t)b * N_ * D_;
    const float* esb = g_es + (size_t)b * N_ * H_;
    int head = lane >> 3;
    float edh = g_ed[(size_t)wid * H_ + head];
    int s0 = rp[n], s1 = rp[n + 1];

    // pass 1: exact max
    float m = -1e30f;
#pragma unroll 4
    for (int p = s0; p < s1; p++) {
        int src = cs[p];
        float e = esb[src * H_ + head] + edh;
        e = e > 0.f ? e : 0.2f * e;
        m = fmaxf(m, e);
    }

    // pass 2: exp + accumulate (independent iterations)
    float d = 0.f;
    float4 acc = make_float4(0.f, 0.f, 0.f, 0.f);
#pragma unroll 2
    for (int p = s0; p < s1; p++) {
        int src = cs[p];
        float e = esb[src * H_ + head] + edh;
        e = e > 0.f ? e : 0.2f * e;
        float pw = __expf(e - m);
        float4 gv = *(const float4*)(gb + (size_t)src * D_ + lane * 4);
        d += pw;
        acc.x += pw * gv.x;
        acc.y += pw * gv.y;
        acc.z += pw * gv.z;
        acc.w += pw * gv.w;
    }

    float inv = 1.f / (d + 1e-16f);
    float mk = mask[b * N_ + n];
    float4 hv = *(const float4*)(h_in + (size_t)wid * D_ + lane * 4);
    float4 o;
    float v;
    v = acc.x * inv + hv.x; o.x = (v > 0.f ? v : expm1f(v)) * mk;
    v = acc.y * inv + hv.y; o.y = (v > 0.f ? v : expm1f(v)) * mk;
    v = acc.z * inv + hv.z; o.z = (v > 0.f ? v : expm1f(v)) * mk;
    v = acc.w * inv + hv.w; o.w = (v > 0.f ? v : expm1f(v)) * mk;
    *(float4*)(h_out + (size_t)wid * D_ + lane * 4) = o;
}

// ---------------- graph embedding (msum fused) -------------------------------
__global__ void graph_accum_kernel(const float* __restrict__ node_emb,
                                   const float* __restrict__ mask) {
    int b = blockIdx.y;
    int o = threadIdx.x;          // 128
    int n0 = blockIdx.x * 250;
    int n1 = n0 + 250;
    float s = 0.f, sm = 0.f;
    for (int n = n0; n < n1; n++) {
        float mk = mask[b * N_ + n];
        s += node_emb[((size_t)(b * N_ + n)) * D_ + o] * mk;
        sm += mk;
    }
    atomicAdd(&g_gacc[b * D_ + o], s);
    if (o == 0) atomicAdd(&g_msum[b], sm);
}

__global__ void finalize_kernel(float* __restrict__ out) {
    int i = blockIdx.x * blockDim.x + threadIdx.x;
    if (i >= B_ * D_) return;
    int b = i / D_;
    float ms = g_msum[b];
    ms = ms < 1.f ? 1.f : ms;
    out[(size_t)B_ * N_ * D_ + i] = g_gacc[i] / ms;
}

// ---------------- launch -----------------------------------------------------
static float* symf(const void* s) { void* p = nullptr; cudaGetSymbolAddress(&p, s); return (float*)p; }

extern "C" void kernel_launch(void* const* d_in, const int* in_sizes, int n_in,
                              void* d_out, int out_size) {
    const float* node_features = (const float*)d_in[0];
    const int*   edge_index    = (const int*)d_in[1];
    const int*   node_types    = (const int*)d_in[2];
    const float* node_mask     = (const float*)d_in[3];
    const float* type_embed    = (const float*)d_in[4];
    const float* in_W          = (const float*)d_in[5];
    const float* in_b          = (const float*)d_in[6];
    const float* gat_W         = (const float*)d_in[7];
    const float* gat_b         = (const float*)d_in[8];
    const float* a_src         = (const float*)d_in[9];
    const float* a_dst         = (const float*)d_in[10];
    const float* out_W         = (const float*)d_in[11];
    const float* out_b         = (const float*)d_in[12];
    float* out = (float*)d_out;

    float* h0   = symf(g_h0);
    float* h1   = symf(g_h1);
    float* gbuf = symf(g_gbuf);

    const int M = B_ * N_;
    const int gemm_grid = (M + 127) / 128;

    const int SMEM64  = (128 * (64 + 4)  + 64  * 136) * 4;
    const int SMEM128 = (128 * (128 + 4) + 128 * 136) * 4;
    cudaFuncSetAttribute(gemm_tc<64>,
                         cudaFuncAttributeMaxDynamicSharedMemorySize, SMEM64);
    cudaFuncSetAttribute(gemm_tc<128>,
                         cudaFuncAttributeMaxDynamicSharedMemorySize, SMEM128);

    // init + CSR build (dst is layer-invariant -> build once, reuse twice)
    zero_kernel<<<(B_ * N_ + 255) / 256, 256>>>();
    count_kernel<<<(B_ * E_ + 255) / 256, 256>>>(edge_index);
    scan_kernel<<<B_, 1024>>>();
    scatter_kernel<<<(B_ * E_ + 255) / 256, 256>>>(edge_index);

    // input projection + type embedding
    gemm_tc<64><<<gemm_grid, 256, SMEM64>>>(node_features, in_W, in_b, h0,
                                            M, node_types, type_embed,
                                            nullptr, nullptr);

    const int warps_grid = (B_ * N_ * 32 + 255) / 256;

    // layer 0 (gemm writes gbuf AND g_es/g_ed)
    gemm_tc<128><<<gemm_grid, 256, SMEM128>>>(h0, gat_W, gat_b, gbuf, M,
                                              nullptr, nullptr, a_src, a_dst);
    agg_kernel<<<warps_grid, 256>>>(gbuf, h0, node_mask, h1);

    // layer 1
    gemm_tc<128><<<gemm_grid, 256, SMEM128>>>(h1, gat_W + D_ * D_, gat_b + D_,
                                              gbuf, M, nullptr, nullptr,
                                              a_src + H_ * (D_ / H_),
                                              a_dst + H_ * (D_ / H_));
    agg_kernel<<<warps_grid, 256>>>(gbuf, h1, node_mask, h0);

    // output projection -> node_emb (directly into d_out)
    gemm_tc<128><<<gemm_grid, 256, SMEM128>>>(h0, out_W, out_b, out, M,
                                              nullptr, nullptr,
                                              nullptr, nullptr);

    // graph embedding
    dim3 gg(40, B_);
    graph_accum_kernel<<<gg, 128>>>(out, node_mask);
    finalize_kernel<<<2, 256>>>(out);
}

// round 15
// speedup vs baseline: 1.8884x; 1.0630x over previous
#include <cuda_runtime.h>
#include <math.h>

#define B_ 4
#define N_ 10000
#define E_ 160000
#define F_ 64
#define D_ 128
#define H_ 4

// ---------------- scratch (static device globals; no allocation) ------------
// Invariant: every buffer that must start zeroed is zero at module load AND
// re-zeroed by its consumer within the same launch -> graph replays see zeros.
__device__ float g_h0[B_ * N_ * D_];
__device__ float g_h1[B_ * N_ * D_];
__device__ float g_gbuf[B_ * N_ * D_];
__device__ float g_es[B_ * N_ * H_];
__device__ float g_ed[B_ * N_ * H_];
__device__ int   g_deg[B_ * N_];
__device__ int   g_rowptr[B_ * (N_ + 1)];
__device__ int   g_fill[B_ * N_];
__device__ int   g_csr[B_ * E_];
__device__ float g_gacc[B_ * D_];
__device__ float g_msum[B_];

// ---------------- CSR build: count -> scan -> scatter -----------------------
// 4 edges per thread, int4 loads (MLP=4 on the latency-bound atomic path)
__global__ void count_kernel(const int* __restrict__ ei) {
    int i = blockIdx.x * blockDim.x + threadIdx.x;
    if (i >= B_ * (E_ / 4)) return;
    int b = i / (E_ / 4), e4 = (i - b * (E_ / 4)) * 4;
    int4 d4 = *(const int4*)(ei + (size_t)b * 2 * E_ + E_ + e4);
    int* deg = g_deg + b * N_;
    atomicAdd(&deg[d4.x], 1);
    atomicAdd(&deg[d4.y], 1);
    atomicAdd(&deg[d4.z], 1);
    atomicAdd(&deg[d4.w], 1);
}

// warp-shuffle scan, 1024 threads per batch; zeroes g_deg after consuming
__global__ __launch_bounds__(1024) void scan_kernel() {
    int b = blockIdx.x;
    int tid = threadIdx.x, lane = tid & 31, wid = tid >> 5;
    __shared__ int wsum[32];
    __shared__ int s_carry, s_tot;
    if (tid == 0) s_carry = 0;
    __syncthreads();
    for (int base = 0; base < N_; base += 1024) {
        int i = base + tid;
        int v = 0;
        if (i < N_) {
            v = g_deg[b * N_ + i];
            g_deg[b * N_ + i] = 0;        // restore zero for next launch
        }
        int inc = v;
#pragma unroll
        for (int o = 1; o < 32; o <<= 1) {
            int t = __shfl_up_sync(0xffffffffu, inc, o);
            if (lane >= o) inc += t;
        }
        if (lane == 31) wsum[wid] = inc;
        __syncthreads();
        if (wid == 0) {
            int sv = wsum[lane];
            int si = sv;
#pragma unroll
            for (int o = 1; o < 32; o <<= 1) {
                int t = __shfl_up_sync(0xffffffffu, si, o);
                if (lane >= o) si += t;
            }
            wsum[lane] = si - sv;
            if (lane == 31) s_tot = si;
        }
        __syncthreads();
        int excl = s_carry + wsum[wid] + inc - v;
        if (i < N_) {
            g_rowptr[b * (N_ + 1) + i] = excl;
            g_fill[b * N_ + i] = excl;
        }
        __syncthreads();
        if (tid == 0) s_carry += s_tot;
        __syncthreads();
    }
    if (tid == 0) g_rowptr[b * (N_ + 1) + N_] = s_carry;
}

__global__ void scatter_kernel(const int* __restrict__ ei) {
    int i = blockIdx.x * blockDim.x + threadIdx.x;
    if (i >= B_ * (E_ / 4)) return;
    int b = i / (E_ / 4), e4 = (i - b * (E_ / 4)) * 4;
    const int* base = ei + (size_t)b * 2 * E_;
    int4 s4 = *(const int4*)(base + e4);
    int4 d4 = *(const int4*)(base + E_ + e4);
    int* fill = g_fill + b * N_;
    int* csr = g_csr + (size_t)b * E_;
    int p0 = atomicAdd(&fill[d4.x], 1);
    int p1 = atomicAdd(&fill[d4.y], 1);
    int p2 = atomicAdd(&fill[d4.z], 1);
    int p3 = atomicAdd(&fill[d4.w], 1);
    csr[p0] = s4.x;
    csr[p1] = s4.y;
    csr[p2] = s4.z;
    csr[p3] = s4.w;
}

// ---------------- tf32 tensor-core GEMM (+ fused e_s/e_d epilogue) ----------
__device__ __forceinline__ unsigned f2tf(float x) {
    unsigned u;
    asm("cvt.rna.tf32.f32 %0, %1;" : "=r"(u) : "f"(x));
    return u;
}

template <int K>
__global__ __launch_bounds__(256, 1) void gemm_tc(
    const float* __restrict__ A, const float* __restrict__ W,
    const float* __restrict__ bias, float* __restrict__ C, int M,
    const int* __restrict__ types, const float* __restrict__ tembed,
    const float* __restrict__ aS, const float* __restrict__ aD)
{
    constexpr int KP = K + 4;
    constexpr int NP = 136;
    extern __shared__ unsigned smem[];
    unsigned* As = smem;                 // [128][KP]
    unsigned* Ws = smem + 128 * KP;      // [K][NP]

    const int tid = threadIdx.x;
    const int lane = tid & 31;
    const int warp = tid >> 5;
    const int mblk = (warp >> 1) * 32;
    const int nblk = (warp & 1) * 64;
    const int row0 = blockIdx.x * 128;
    const int g4 = lane >> 2;
    const int q4 = lane & 3;

    constexpr int K4 = K / 4;
#pragma unroll
    for (int it = 0; it < (128 * K4) / 256; it++) {
        int idx = tid + it * 256;
        int r = idx / K4, c4 = (idx % K4) * 4;
        float4 v = make_float4(0.f, 0.f, 0.f, 0.f);
        if (row0 + r < M) v = *(const float4*)(A + (size_t)(row0 + r) * K + c4);
        uint4 u;
        u.x = f2tf(v.x); u.y = f2tf(v.y); u.z = f2tf(v.z); u.w = f2tf(v.w);
        *(uint4*)(As + r * KP + c4) = u;
    }
#pragma unroll
    for (int it = 0; it < (K * 32) / 256; it++) {
        int idx = tid + it * 256;
        int r = idx >> 5, c4 = (idx & 31) * 4;
        float4 v = *(const float4*)(W + (size_t)r * 128 + c4);
        uint4 u;
        u.x = f2tf(v.x); u.y = f2tf(v.y); u.z = f2tf(v.z); u.w = f2tf(v.w);
        *(uint4*)(Ws + r * NP + c4) = u;
    }
    __syncthreads();

    float acc[2][8][4];
#pragma unroll
    for (int mt = 0; mt < 2; mt++)
#pragma unroll
        for (int nt = 0; nt < 8; nt++)
#pragma unroll
            for (int c = 0; c < 4; c++) acc[mt][nt][c] = 0.f;

#pragma unroll 4
    for (int k0 = 0; k0 < K; k0 += 8) {
        unsigned a[2][4];
#pragma unroll
        for (int mt = 0; mt < 2; mt++) {
            int r = mblk + mt * 16 + g4;
            int c = k0 + q4;
            a[mt][0] = As[r * KP + c];
            a[mt][1] = As[(r + 8) * KP + c];
            a[mt][2] = As[r * KP + c + 4];
            a[mt][3] = As[(r + 8) * KP + c + 4];
        }
#pragma unroll
        for (int nt = 0; nt < 8; nt++) {
            int n = nblk + nt * 8 + g4;
            unsigned b0 = Ws[(k0 + q4) * NP + n];
            unsigned b1 = Ws[(k0 + 4 + q4) * NP + n];
#pragma unroll
            for (int mt = 0; mt < 2; mt++) {
                float* cc = acc[mt][nt];
                asm volatile(
                    "mma.sync.aligned.m16n8k8.row.col.f32.tf32.tf32.f32 "
                    "{%0,%1,%2,%3}, {%4,%5,%6,%7}, {%8,%9}, {%0,%1,%2,%3};"
                    : "+f"(cc[0]), "+f"(cc[1]), "+f"(cc[2]), "+f"(cc[3])
                    : "r"(a[mt][0]), "r"(a[mt][1]), "r"(a[mt][2]), "r"(a[mt][3]),
                      "r"(b0), "r"(b1));
            }
        }
    }

    const int hb0 = nblk >> 5;   // head base for this warp: 0 or 2
#pragma unroll
    for (int mt = 0; mt < 2; mt++) {
        int rt = row0 + mblk + mt * 16 + g4;
        int rb = rt + 8;
        const float* tet = nullptr;
        const float* teb = nullptr;
        if (types) {
            if (rt < M) tet = tembed + (size_t)types[rt] * 128;
            if (rb < M) teb = tembed + (size_t)types[rb] * 128;
        }
        float es_t[2] = {0.f, 0.f}, ed_t[2] = {0.f, 0.f};
        float es_b[2] = {0.f, 0.f}, ed_b[2] = {0.f, 0.f};
#pragma unroll
        for (int nt = 0; nt < 8; nt++) {
            int cbase = nblk + nt * 8 + q4 * 2;
            float b0 = bias[cbase], b1 = bias[cbase + 1];
            float o0 = acc[mt][nt][0] + b0;
            float o1 = acc[mt][nt][1] + b1;
            float o2 = acc[mt][nt][2] + b0;
            float o3 = acc[mt][nt][3] + b1;
            if (tet) { o0 += tet[cbase]; o1 += tet[cbase + 1]; }
            if (teb) { o2 += teb[cbase]; o3 += teb[cbase + 1]; }
            if (rt < M) *(float2*)(C + (size_t)rt * 128 + cbase) = make_float2(o0, o1);
            if (rb < M) *(float2*)(C + (size_t)rb * 128 + cbase) = make_float2(o2, o3);
            if (aS) {
                int h = nt >> 2;
                int cw = (nt & 3) * 8 + q4 * 2;
                int hg = (hb0 + h) * 32 + cw;
                float as0 = aS[hg], as1 = aS[hg + 1];
                float ad0 = aD[hg], ad1 = aD[hg + 1];
                es_t[h] += o0 * as0 + o1 * as1;
                ed_t[h] += o0 * ad0 + o1 * ad1;
                es_b[h] += o2 * as0 + o3 * as1;
                ed_b[h] += o2 * ad0 + o3 * ad1;
            }
        }
        if (aS) {
#pragma unroll
            for (int h = 0; h < 2; h++) {
                es_t[h] += __shfl_xor_sync(0xffffffffu, es_t[h], 1);
                es_t[h] += __shfl_xor_sync(0xffffffffu, es_t[h], 2);
                ed_t[h] += __shfl_xor_sync(0xffffffffu, ed_t[h], 1);
                ed_t[h] += __shfl_xor_sync(0xffffffffu, ed_t[h], 2);
                es_b[h] += __shfl_xor_sync(0xffffffffu, es_b[h], 1);
                es_b[h] += __shfl_xor_sync(0xffffffffu, es_b[h], 2);
                ed_b[h] += __shfl_xor_sync(0xffffffffu, ed_b[h], 1);
                ed_b[h] += __shfl_xor_sync(0xffffffffu, ed_b[h], 2);
            }
            if (q4 == 0) {
                if (rt < M) {
                    *(float2*)(g_es + (size_t)rt * H_ + hb0) = make_float2(es_t[0], es_t[1]);
                    *(float2*)(g_ed + (size_t)rt * H_ + hb0) = make_float2(ed_t[0], ed_t[1]);
                }
                if (rb < M) {
                    *(float2*)(g_es + (size_t)rb * H_ + hb0) = make_float2(es_b[0], es_b[1]);
                    *(float2*)(g_ed + (size_t)rb * H_ + hb0) = make_float2(ed_b[0], ed_b[1]);
                }
            }
        }
    }
}

// ---------------- GAT aggregation: warp/node, two-pass softmax, no atomics --
// Pass 1: exact segment max, split across the 8 lanes of each head group.
// Pass 2: exp+accumulate, independent iterations -> high MLP.
__global__ __launch_bounds__(256) void agg_kernel(const float* __restrict__ g,
                                                  const float* __restrict__ h_in,
                                                  const float* __restrict__ mask,
                                                  float* __restrict__ h_out) {
    int wid = (blockIdx.x * blockDim.x + threadIdx.x) >> 5;
    int lane = threadIdx.x & 31;
    if (wid >= B_ * N_) return;
    int b = wid / N_, n = wid - b * N_;
    const int* rp = g_rowptr + b * (N_ + 1);
    const int* cs = g_csr + (size_t)b * E_;
    const float* gb = g + (size_t)b * N_ * D_;
    const float* esb = g_es + (size_t)b * N_ * H_;
    int head = lane >> 3;
    int lq = lane & 7;
    float edh = g_ed[(size_t)wid * H_ + head];
    int s0 = rp[n], s1 = rp[n + 1];

    // pass 1: exact max, 8-way parallel within head group
    float m = -1e30f;
    for (int p = s0 + lq; p < s1; p += 8) {
        int src = cs[p];
        float e = esb[src * H_ + head] + edh;
        e = e > 0.f ? e : 0.2f * e;
        m = fmaxf(m, e);
    }
    m = fmaxf(m, __shfl_xor_sync(0xffffffffu, m, 1));
    m = fmaxf(m, __shfl_xor_sync(0xffffffffu, m, 2));
    m = fmaxf(m, __shfl_xor_sync(0xffffffffu, m, 4));

    // pass 2: exp + accumulate (independent iterations)
    float d = 0.f;
    float4 acc = make_float4(0.f, 0.f, 0.f, 0.f);
#pragma unroll 4
    for (int p = s0; p < s1; p++) {
        int src = cs[p];
        float e = esb[src * H_ + head] + edh;
        e = e > 0.f ? e : 0.2f * e;
        float pw = __expf(e - m);
        float4 gv = *(const float4*)(gb + (size_t)src * D_ + lane * 4);
        d += pw;
        acc.x += pw * gv.x;
        acc.y += pw * gv.y;
        acc.z += pw * gv.z;
        acc.w += pw * gv.w;
    }

    float inv = 1.f / (d + 1e-16f);
    float mk = mask[b * N_ + n];
    float4 hv = *(const float4*)(h_in + (size_t)wid * D_ + lane * 4);
    float4 o;
    float v;
    v = acc.x * inv + hv.x; o.x = (v > 0.f ? v : expm1f(v)) * mk;
    v = acc.y * inv + hv.y; o.y = (v > 0.f ? v : expm1f(v)) * mk;
    v = acc.z * inv + hv.z; o.z = (v > 0.f ? v : expm1f(v)) * mk;
    v = acc.w * inv + hv.w; o.w = (v > 0.f ? v : expm1f(v)) * mk;
    *(float4*)(h_out + (size_t)wid * D_ + lane * 4) = o;
}

// ---------------- graph embedding (msum fused) -------------------------------
__global__ void graph_accum_kernel(const float* __restrict__ node_emb,
                                   const float* __restrict__ mask) {
    int b = blockIdx.y;
    int o = threadIdx.x;          // 128
    int n0 = blockIdx.x * 250;
    int n1 = n0 + 250;
    float s = 0.f, sm = 0.f;
    for (int n = n0; n < n1; n++) {
        float mk = mask[b * N_ + n];
        s += node_emb[((size_t)(b * N_ + n)) * D_ + o] * mk;
        sm += mk;
    }
    atomicAdd(&g_gacc[b * D_ + o], s);
    if (o == 0) atomicAdd(&g_msum[b], sm);
}

// reads + restores-to-zero g_gacc/g_msum (512 threads == B_*D_ exactly)
__global__ void finalize_kernel(float* __restrict__ out) {
    int i = blockIdx.x * blockDim.x + threadIdx.x;
    int b = i / D_;
    float ms = g_msum[b];
    ms = ms < 1.f ? 1.f : ms;
    out[(size_t)B_ * N_ * D_ + i] = g_gacc[i] / ms;
    g_gacc[i] = 0.f;
    __syncthreads();                     // all reads of g_msum[b] done
    if ((i & (D_ - 1)) == 0) g_msum[b] = 0.f;
}

// ---------------- launch -----------------------------------------------------
static float* symf(const void* s) { void* p = nullptr; cudaGetSymbolAddress(&p, s); return (float*)p; }

extern "C" void kernel_launch(void* const* d_in, const int* in_sizes, int n_in,
                              void* d_out, int out_size) {
    const float* node_features = (const float*)d_in[0];
    const int*   edge_index    = (const int*)d_in[1];
    const int*   node_types    = (const int*)d_in[2];
    const float* node_mask     = (const float*)d_in[3];
    const float* type_embed    = (const float*)d_in[4];
    const float* in_W          = (const float*)d_in[5];
    const float* in_b          = (const float*)d_in[6];
    const float* gat_W         = (const float*)d_in[7];
    const float* gat_b         = (const float*)d_in[8];
    const float* a_src         = (const float*)d_in[9];
    const float* a_dst         = (const float*)d_in[10];
    const float* out_W         = (const float*)d_in[11];
    const float* out_b         = (const float*)d_in[12];
    float* out = (float*)d_out;

    float* h0   = symf(g_h0);
    float* h1   = symf(g_h1);
    float* gbuf = symf(g_gbuf);

    const int M = B_ * N_;
    const int gemm_grid = (M + 127) / 128;

    const int SMEM64  = (128 * (64 + 4)  + 64  * 136) * 4;
    const int SMEM128 = (128 * (128 + 4) + 128 * 136) * 4;
    cudaFuncSetAttribute(gemm_tc<64>,
                         cudaFuncAttributeMaxDynamicSharedMemorySize, SMEM64);
    cudaFuncSetAttribute(gemm_tc<128>,
                         cudaFuncAttributeMaxDynamicSharedMemorySize, SMEM128);

    // CSR build (dst is layer-invariant -> build once, reuse twice)
    const int e4_grid = (B_ * (E_ / 4) + 255) / 256;
    count_kernel<<<e4_grid, 256>>>(edge_index);
    scan_kernel<<<B_, 1024>>>();
    scatter_kernel<<<e4_grid, 256>>>(edge_index);

    // input projection + type embedding
    gemm_tc<64><<<gemm_grid, 256, SMEM64>>>(node_features, in_W, in_b, h0,
                                            M, node_types, type_embed,
                                            nullptr, nullptr);

    const int warps_grid = (B_ * N_ * 32 + 255) / 256;

    // layer 0 (gemm writes gbuf AND g_es/g_ed)
    gemm_tc<128><<<gemm_grid, 256, SMEM128>>>(h0, gat_W, gat_b, gbuf, M,
                                              nullptr, nullptr, a_src, a_dst);
    agg_kernel<<<warps_grid, 256>>>(gbuf, h0, node_mask, h1);

    // layer 1
    gemm_tc<128><<<gemm_grid, 256, SMEM128>>>(h1, gat_W + D_ * D_, gat_b + D_,
                                              gbuf, M, nullptr, nullptr,
                                              a_src + H_ * (D_ / H_),
                                              a_dst + H_ * (D_ / H_));
    agg_kernel<<<warps_grid, 256>>>(gbuf, h1, node_mask, h0);

    // output projection -> node_emb (directly into d_out)
    gemm_tc<128><<<gemm_grid, 256, SMEM128>>>(h0, out_W, out_b, out, M,
                                              nullptr, nullptr,
                                              nullptr, nullptr);

    // graph embedding
    dim3 gg(40, B_);
    graph_accum_kernel<<<gg, 128>>>(out, node_mask);
    finalize_kernel<<<2, 256>>>(out);
}

// round 16
// speedup vs baseline: 1.8987x; 1.0055x over previous
#include <cuda_runtime.h>
#include <math.h>

#define B_ 4
#define N_ 10000
#define E_ 160000
#define F_ 64
#define D_ 128
#define H_ 4

// ---------------- scratch (static device globals; no allocation) ------------
// Invariant: every buffer that must start zeroed is zero at module load AND
// re-zeroed by its consumer within the same launch -> graph replays see zeros.
__device__ float g_h0[B_ * N_ * D_];
__device__ float g_h1[B_ * N_ * D_];
__device__ float g_gbuf[B_ * N_ * D_];
__device__ float g_es[B_ * N_ * H_];
__device__ float g_ed[B_ * N_ * H_];
__device__ int   g_deg[B_ * N_];
__device__ int   g_rowptr[B_ * (N_ + 1)];
__device__ int   g_fill[B_ * N_];
__device__ int   g_csr[B_ * E_];
__device__ float g_gacc[B_ * D_];
__device__ float g_msum[B_];

// ---------------- CSR build: count -> scan -> scatter -----------------------
// 4 edges per thread, int4 loads (MLP=4 on the latency-bound atomic path)
__global__ void count_kernel(const int* __restrict__ ei) {
    int i = blockIdx.x * blockDim.x + threadIdx.x;
    if (i >= B_ * (E_ / 4)) return;
    int b = i / (E_ / 4), e4 = (i - b * (E_ / 4)) * 4;
    int4 d4 = *(const int4*)(ei + (size_t)b * 2 * E_ + E_ + e4);
    int* deg = g_deg + b * N_;
    atomicAdd(&deg[d4.x], 1);
    atomicAdd(&deg[d4.y], 1);
    atomicAdd(&deg[d4.z], 1);
    atomicAdd(&deg[d4.w], 1);
}

// warp-shuffle scan, 1024 threads per batch; zeroes g_deg after consuming
__global__ __launch_bounds__(1024) void scan_kernel() {
    int b = blockIdx.x;
    int tid = threadIdx.x, lane = tid & 31, wid = tid >> 5;
    __shared__ int wsum[32];
    __shared__ int s_carry, s_tot;
    if (tid == 0) s_carry = 0;
    __syncthreads();
    for (int base = 0; base < N_; base += 1024) {
        int i = base + tid;
        int v = 0;
        if (i < N_) {
            v = g_deg[b * N_ + i];
            g_deg[b * N_ + i] = 0;        // restore zero for next launch
        }
        int inc = v;
#pragma unroll
        for (int o = 1; o < 32; o <<= 1) {
            int t = __shfl_up_sync(0xffffffffu, inc, o);
            if (lane >= o) inc += t;
        }
        if (lane == 31) wsum[wid] = inc;
        __syncthreads();
        if (wid == 0) {
            int sv = wsum[lane];
            int si = sv;
#pragma unroll
            for (int o = 1; o < 32; o <<= 1) {
                int t = __shfl_up_sync(0xffffffffu, si, o);
                if (lane >= o) si += t;
            }
            wsum[lane] = si - sv;
            if (lane == 31) s_tot = si;
        }
        __syncthreads();
        int excl = s_carry + wsum[wid] + inc - v;
        if (i < N_) {
            g_rowptr[b * (N_ + 1) + i] = excl;
            g_fill[b * N_ + i] = excl;
        }
        __syncthreads();
        if (tid == 0) s_carry += s_tot;
        __syncthreads();
    }
    if (tid == 0) g_rowptr[b * (N_ + 1) + N_] = s_carry;
}

__global__ void scatter_kernel(const int* __restrict__ ei) {
    int i = blockIdx.x * blockDim.x + threadIdx.x;
    if (i >= B_ * (E_ / 4)) return;
    int b = i / (E_ / 4), e4 = (i - b * (E_ / 4)) * 4;
    const int* base = ei + (size_t)b * 2 * E_;
    int4 s4 = *(const int4*)(base + e4);
    int4 d4 = *(const int4*)(base + E_ + e4);
    int* fill = g_fill + b * N_;
    int* csr = g_csr + (size_t)b * E_;
    int p0 = atomicAdd(&fill[d4.x], 1);
    int p1 = atomicAdd(&fill[d4.y], 1);
    int p2 = atomicAdd(&fill[d4.z], 1);
    int p3 = atomicAdd(&fill[d4.w], 1);
    csr[p0] = s4.x;
    csr[p1] = s4.y;
    csr[p2] = s4.z;
    csr[p3] = s4.w;
}

// ---------------- tf32 tensor-core GEMM (+ fused e_s/e_d epilogue) ----------
// 512 threads, 16 warps in 4x4 layout, warp tile 32x32 (one head per warp).
__device__ __forceinline__ unsigned f2tf(float x) {
    unsigned u;
    asm("cvt.rna.tf32.f32 %0, %1;" : "=r"(u) : "f"(x));
    return u;
}

template <int K>
__global__ __launch_bounds__(512, 1) void gemm_tc(
    const float* __restrict__ A, const float* __restrict__ W,
    const float* __restrict__ bias, float* __restrict__ C, int M,
    const int* __restrict__ types, const float* __restrict__ tembed,
    const float* __restrict__ aS, const float* __restrict__ aD)
{
    constexpr int KP = K + 4;
    constexpr int NP = 136;
    extern __shared__ unsigned smem[];
    unsigned* As = smem;                 // [128][KP]
    unsigned* Ws = smem + 128 * KP;      // [K][NP]

    const int tid = threadIdx.x;
    const int lane = tid & 31;
    const int warp = tid >> 5;
    const int mblk = (warp >> 2) * 32;
    const int nblk = (warp & 3) * 32;
    const int head = warp & 3;           // warp's 32 cols == one head
    const int row0 = blockIdx.x * 128;
    const int g4 = lane >> 2;
    const int q4 = lane & 3;

    constexpr int K4 = K / 4;
#pragma unroll
    for (int it = 0; it < (128 * K4) / 512; it++) {
        int idx = tid + it * 512;
        int r = idx / K4, c4 = (idx % K4) * 4;
        float4 v = make_float4(0.f, 0.f, 0.f, 0.f);
        if (row0 + r < M) v = *(const float4*)(A + (size_t)(row0 + r) * K + c4);
        uint4 u;
        u.x = f2tf(v.x); u.y = f2tf(v.y); u.z = f2tf(v.z); u.w = f2tf(v.w);
        *(uint4*)(As + r * KP + c4) = u;
    }
#pragma unroll
    for (int it = 0; it < (K * 32) / 512; it++) {
        int idx = tid + it * 512;
        int r = idx >> 5, c4 = (idx & 31) * 4;
        float4 v = *(const float4*)(W + (size_t)r * 128 + c4);
        uint4 u;
        u.x = f2tf(v.x); u.y = f2tf(v.y); u.z = f2tf(v.z); u.w = f2tf(v.w);
        *(uint4*)(Ws + r * NP + c4) = u;
    }
    __syncthreads();

    float acc[2][4][4];
#pragma unroll
    for (int mt = 0; mt < 2; mt++)
#pragma unroll
        for (int nt = 0; nt < 4; nt++)
#pragma unroll
            for (int c = 0; c < 4; c++) acc[mt][nt][c] = 0.f;

#pragma unroll 4
    for (int k0 = 0; k0 < K; k0 += 8) {
        unsigned a[2][4];
#pragma unroll
        for (int mt = 0; mt < 2; mt++) {
            int r = mblk + mt * 16 + g4;
            int c = k0 + q4;
            a[mt][0] = As[r * KP + c];
            a[mt][1] = As[(r + 8) * KP + c];
            a[mt][2] = As[r * KP + c + 4];
            a[mt][3] = As[(r + 8) * KP + c + 4];
        }
#pragma unroll
        for (int nt = 0; nt < 4; nt++) {
            int n = nblk + nt * 8 + g4;
            unsigned b0 = Ws[(k0 + q4) * NP + n];
            unsigned b1 = Ws[(k0 + 4 + q4) * NP + n];
#pragma unroll
            for (int mt = 0; mt < 2; mt++) {
                float* cc = acc[mt][nt];
                asm volatile(
                    "mma.sync.aligned.m16n8k8.row.col.f32.tf32.tf32.f32 "
                    "{%0,%1,%2,%3}, {%4,%5,%6,%7}, {%8,%9}, {%0,%1,%2,%3};"
                    : "+f"(cc[0]), "+f"(cc[1]), "+f"(cc[2]), "+f"(cc[3])
                    : "r"(a[mt][0]), "r"(a[mt][1]), "r"(a[mt][2]), "r"(a[mt][3]),
                      "r"(b0), "r"(b1));
            }
        }
    }

#pragma unroll
    for (int mt = 0; mt < 2; mt++) {
        int rt = row0 + mblk + mt * 16 + g4;
        int rb = rt + 8;
        const float* tet = nullptr;
        const float* teb = nullptr;
        if (types) {
            if (rt < M) tet = tembed + (size_t)types[rt] * 128;
            if (rb < M) teb = tembed + (size_t)types[rb] * 128;
        }
        float es_t = 0.f, ed_t = 0.f, es_b = 0.f, ed_b = 0.f;
#pragma unroll
        for (int nt = 0; nt < 4; nt++) {
            int cbase = nblk + nt * 8 + q4 * 2;
            float b0 = bias[cbase], b1 = bias[cbase + 1];
            float o0 = acc[mt][nt][0] + b0;
            float o1 = acc[mt][nt][1] + b1;
            float o2 = acc[mt][nt][2] + b0;
            float o3 = acc[mt][nt][3] + b1;
            if (tet) { o0 += tet[cbase]; o1 += tet[cbase + 1]; }
            if (teb) { o2 += teb[cbase]; o3 += teb[cbase + 1]; }
            if (rt < M) *(float2*)(C + (size_t)rt * 128 + cbase) = make_float2(o0, o1);
            if (rb < M) *(float2*)(C + (size_t)rb * 128 + cbase) = make_float2(o2, o3);
            if (aS) {
                int hg = head * 32 + nt * 8 + q4 * 2;
                float as0 = aS[hg], as1 = aS[hg + 1];
                float ad0 = aD[hg], ad1 = aD[hg + 1];
                es_t += o0 * as0 + o1 * as1;
                ed_t += o0 * ad0 + o1 * ad1;
                es_b += o2 * as0 + o3 * as1;
                ed_b += o2 * ad0 + o3 * ad1;
            }
        }
        if (aS) {
            es_t += __shfl_xor_sync(0xffffffffu, es_t, 1);
            es_t += __shfl_xor_sync(0xffffffffu, es_t, 2);
            ed_t += __shfl_xor_sync(0xffffffffu, ed_t, 1);
            ed_t += __shfl_xor_sync(0xffffffffu, ed_t, 2);
            es_b += __shfl_xor_sync(0xffffffffu, es_b, 1);
            es_b += __shfl_xor_sync(0xffffffffu, es_b, 2);
            ed_b += __shfl_xor_sync(0xffffffffu, ed_b, 1);
            ed_b += __shfl_xor_sync(0xffffffffu, ed_b, 2);
            if (q4 == 0) {
                if (rt < M) {
                    g_es[(size_t)rt * H_ + head] = es_t;
                    g_ed[(size_t)rt * H_ + head] = ed_t;
                }
                if (rb < M) {
                    g_es[(size_t)rb * H_ + head] = es_b;
                    g_ed[(size_t)rb * H_ + head] = ed_b;
                }
            }
        }
    }
}

// ---------------- GAT aggregation: warp/node, two-pass softmax, no atomics --
// Pass 1: exact segment max, split across the 8 lanes of each head group.
// Pass 2: exp+accumulate, independent iterations -> high MLP.
__global__ __launch_bounds__(256) void agg_kernel(const float* __restrict__ g,
                                                  const float* __restrict__ h_in,
                                                  const float* __restrict__ mask,
                                                  float* __restrict__ h_out) {
    int wid = (blockIdx.x * blockDim.x + threadIdx.x) >> 5;
    int lane = threadIdx.x & 31;
    if (wid >= B_ * N_) return;
    int b = wid / N_, n = wid - b * N_;
    const int* rp = g_rowptr + b * (N_ + 1);
    const int* cs = g_csr + (size_t)b * E_;
    const float* gb = g + (size_t)b * N_ * D_;
    const float* esb = g_es + (size_t)b * N_ * H_;
    int head = lane >> 3;
    int lq = lane & 7;
    float edh = g_ed[(size_t)wid * H_ + head];
    int s0 = rp[n], s1 = rp[n + 1];

    // pass 1: exact max, 8-way parallel within head group
    float m = -1e30f;
    for (int p = s0 + lq; p < s1; p += 8) {
        int src = cs[p];
        float e = esb[src * H_ + head] + edh;
        e = e > 0.f ? e : 0.2f * e;
        m = fmaxf(m, e);
    }
    m = fmaxf(m, __shfl_xor_sync(0xffffffffu, m, 1));
    m = fmaxf(m, __shfl_xor_sync(0xffffffffu, m, 2));
    m = fmaxf(m, __shfl_xor_sync(0xffffffffu, m, 4));

    // pass 2: exp + accumulate (independent iterations)
    float d = 0.f;
    float4 acc = make_float4(0.f, 0.f, 0.f, 0.f);
#pragma unroll 4
    for (int p = s0; p < s1; p++) {
        int src = cs[p];
        float e = esb[src * H_ + head] + edh;
        e = e > 0.f ? e : 0.2f * e;
        float pw = __expf(e - m);
        float4 gv = *(const float4*)(gb + (size_t)src * D_ + lane * 4);
        d += pw;
        acc.x += pw * gv.x;
        acc.y += pw * gv.y;
        acc.z += pw * gv.z;
        acc.w += pw * gv.w;
    }

    float inv = 1.f / (d + 1e-16f);
    float mk = mask[b * N_ + n];
    float4 hv = *(const float4*)(h_in + (size_t)wid * D_ + lane * 4);
    float4 o;
    float v;
    v = acc.x * inv + hv.x; o.x = (v > 0.f ? v : expm1f(v)) * mk;
    v = acc.y * inv + hv.y; o.y = (v > 0.f ? v : expm1f(v)) * mk;
    v = acc.z * inv + hv.z; o.z = (v > 0.f ? v : expm1f(v)) * mk;
    v = acc.w * inv + hv.w; o.w = (v > 0.f ? v : expm1f(v)) * mk;
    *(float4*)(h_out + (size_t)wid * D_ + lane * 4) = o;
}

// ---------------- graph embedding (msum fused) -------------------------------
__global__ void graph_accum_kernel(const float* __restrict__ node_emb,
                                   const float* __restrict__ mask) {
    int b = blockIdx.y;
    int o = threadIdx.x;          // 128
    int n0 = blockIdx.x * 250;
    int n1 = n0 + 250;
    float s = 0.f, sm = 0.f;
    for (int n = n0; n < n1; n++) {
        float mk = mask[b * N_ + n];
        s += node_emb[((size_t)(b * N_ + n)) * D_ + o] * mk;
        sm += mk;
    }
    atomicAdd(&g_gacc[b * D_ + o], s);
    if (o == 0) atomicAdd(&g_msum[b], sm);
}

// reads + restores-to-zero g_gacc/g_msum (512 threads == B_*D_ exactly)
__global__ void finalize_kernel(float* __restrict__ out) {
    int i = blockIdx.x * blockDim.x + threadIdx.x;
    int b = i / D_;
    float ms = g_msum[b];
    ms = ms < 1.f ? 1.f : ms;
    out[(size_t)B_ * N_ * D_ + i] = g_gacc[i] / ms;
    g_gacc[i] = 0.f;
    __syncthreads();                     // all reads of g_msum[b] done
    if ((i & (D_ - 1)) == 0) g_msum[b] = 0.f;
}

// ---------------- launch -----------------------------------------------------
static float* symf(const void* s) { void* p = nullptr; cudaGetSymbolAddress(&p, s); return (float*)p; }

extern "C" void kernel_launch(void* const* d_in, const int* in_sizes, int n_in,
                              void* d_out, int out_size) {
    const float* node_features = (const float*)d_in[0];
    const int*   edge_index    = (const int*)d_in[1];
    const int*   node_types    = (const int*)d_in[2];
    const float* node_mask     = (const float*)d_in[3];
    const float* type_embed    = (const float*)d_in[4];
    const float* in_W          = (const float*)d_in[5];
    const float* in_b          = (const float*)d_in[6];
    const float* gat_W         = (const float*)d_in[7];
    const float* gat_b         = (const float*)d_in[8];
    const float* a_src         = (const float*)d_in[9];
    const float* a_dst         = (const float*)d_in[10];
    const float* out_W         = (const float*)d_in[11];
    const float* out_b         = (const float*)d_in[12];
    float* out = (float*)d_out;

    float* h0   = symf(g_h0);
    float* h1   = symf(g_h1);
    float* gbuf = symf(g_gbuf);

    const int M = B_ * N_;
    const int gemm_grid = (M + 127) / 128;

    const int SMEM64  = (128 * (64 + 4)  + 64  * 136) * 4;
    const int SMEM128 = (128 * (128 + 4) + 128 * 136) * 4;
    cudaFuncSetAttribute(gemm_tc<64>,
                         cudaFuncAttributeMaxDynamicSharedMemorySize, SMEM64);
    cudaFuncSetAttribute(gemm_tc<128>,
                         cudaFuncAttributeMaxDynamicSharedMemorySize, SMEM128);

    // CSR build (dst is layer-invariant -> build once, reuse twice)
    const int e4_grid = (B_ * (E_ / 4) + 255) / 256;
    count_kernel<<<e4_grid, 256>>>(edge_index);
    scan_kernel<<<B_, 1024>>>();
    scatter_kernel<<<e4_grid, 256>>>(edge_index);

    // input projection + type embedding
    gemm_tc<64><<<gemm_grid, 512, SMEM64>>>(node_features, in_W, in_b, h0,
                                            M, node_types, type_embed,
                                            nullptr, nullptr);

    const int warps_grid = (B_ * N_ * 32 + 255) / 256;

    // layer 0 (gemm writes gbuf AND g_es/g_ed)
    gemm_tc<128><<<gemm_grid, 512, SMEM128>>>(h0, gat_W, gat_b, gbuf, M,
                                              nullptr, nullptr, a_src, a_dst);
    agg_kernel<<<warps_grid, 256>>>(gbuf, h0, node_mask, h1);

    // layer 1
    gemm_tc<128><<<gemm_grid, 512, SMEM128>>>(h1, gat_W + D_ * D_, gat_b + D_,
                                              gbuf, M, nullptr, nullptr,
                                              a_src + H_ * (D_ / H_),
                                              a_dst + H_ * (D_ / H_));
    agg_kernel<<<warps_grid, 256>>>(gbuf, h1, node_mask, h0);

    // output projection -> node_emb (directly into d_out)
    gemm_tc<128><<<gemm_grid, 512, SMEM128>>>(h0, out_W, out_b, out, M,
                                              nullptr, nullptr,
                                              nullptr, nullptr);

    // graph embedding
    dim3 gg(40, B_);
    graph_accum_kernel<<<gg, 128>>>(out, node_mask);
    finalize_kernel<<<2, 256>>>(out);
}

// round 17
// speedup vs baseline: 1.9642x; 1.0345x over previous
#include <cuda_runtime.h>
#include <math.h>

#define B_ 4
#define N_ 10000
#define E_ 160000
#define F_ 64
#define D_ 128
#define H_ 4

// ---------------- scratch (static device globals; no allocation) ------------
// Invariant: every buffer that must start zeroed is zero at module load AND
// re-zeroed by its consumer within the same launch -> graph replays see zeros.
__device__ float g_h0[B_ * N_ * D_];
__device__ float g_h1[B_ * N_ * D_];
__device__ float g_gbuf[B_ * N_ * D_];
__device__ float g_es[B_ * N_ * H_];
__device__ float g_ed[B_ * N_ * H_];
__device__ int   g_deg[B_ * N_];
__device__ int   g_rowptr[B_ * (N_ + 1)];
__device__ int   g_fill[B_ * N_];
__device__ int   g_csr[B_ * E_];
__device__ float g_gacc[B_ * D_];
__device__ float g_msum[B_];

// ---------------- CSR build: count -> scan -> scatter -----------------------
// 4 edges per thread, int4 loads (MLP=4 on the latency-bound atomic path)
__global__ void count_kernel(const int* __restrict__ ei) {
    int i = blockIdx.x * blockDim.x + threadIdx.x;
    if (i >= B_ * (E_ / 4)) return;
    int b = i / (E_ / 4), e4 = (i - b * (E_ / 4)) * 4;
    int4 d4 = *(const int4*)(ei + (size_t)b * 2 * E_ + E_ + e4);
    int* deg = g_deg + b * N_;
    atomicAdd(&deg[d4.x], 1);
    atomicAdd(&deg[d4.y], 1);
    atomicAdd(&deg[d4.z], 1);
    atomicAdd(&deg[d4.w], 1);
}

// warp-shuffle scan, 1024 threads per batch; zeroes g_deg after consuming
__global__ __launch_bounds__(1024) void scan_kernel() {
    int b = blockIdx.x;
    int tid = threadIdx.x, lane = tid & 31, wid = tid >> 5;
    __shared__ int wsum[32];
    __shared__ int s_carry, s_tot;
    if (tid == 0) s_carry = 0;
    __syncthreads();
    for (int base = 0; base < N_; base += 1024) {
        int i = base + tid;
        int v = 0;
        if (i < N_) {
            v = g_deg[b * N_ + i];
            g_deg[b * N_ + i] = 0;        // restore zero for next launch
        }
        int inc = v;
#pragma unroll
        for (int o = 1; o < 32; o <<= 1) {
            int t = __shfl_up_sync(0xffffffffu, inc, o);
            if (lane >= o) inc += t;
        }
        if (lane == 31) wsum[wid] = inc;
        __syncthreads();
        if (wid == 0) {
            int sv = wsum[lane];
            int si = sv;
#pragma unroll
            for (int o = 1; o < 32; o <<= 1) {
                int t = __shfl_up_sync(0xffffffffu, si, o);
                if (lane >= o) si += t;
            }
            wsum[lane] = si - sv;
            if (lane == 31) s_tot = si;
        }
        __syncthreads();
        int excl = s_carry + wsum[wid] + inc - v;
        if (i < N_) {
            g_rowptr[b * (N_ + 1) + i] = excl;
            g_fill[b * N_ + i] = excl;
        }
        __syncthreads();
        if (tid == 0) s_carry += s_tot;
        __syncthreads();
    }
    if (tid == 0) g_rowptr[b * (N_ + 1) + N_] = s_carry;
}

__global__ void scatter_kernel(const int* __restrict__ ei) {
    int i = blockIdx.x * blockDim.x + threadIdx.x;
    if (i >= B_ * (E_ / 4)) return;
    int b = i / (E_ / 4), e4 = (i - b * (E_ / 4)) * 4;
    const int* base = ei + (size_t)b * 2 * E_;
    int4 s4 = *(const int4*)(base + e4);
    int4 d4 = *(const int4*)(base + E_ + e4);
    int* fill = g_fill + b * N_;
    int* csr = g_csr + (size_t)b * E_;
    int p0 = atomicAdd(&fill[d4.x], 1);
    int p1 = atomicAdd(&fill[d4.y], 1);
    int p2 = atomicAdd(&fill[d4.z], 1);
    int p3 = atomicAdd(&fill[d4.w], 1);
    csr[p0] = s4.x;
    csr[p1] = s4.y;
    csr[p2] = s4.z;
    csr[p3] = s4.w;
}

// ---------------- tf32 tensor-core GEMM (+ fused e_s/e_d epilogue) ----------
// BM=64, 256 threads, 8 warps in 2x4 layout, warp tile 32x32 (one head/warp).
// Small smem (52KB / 103KB) -> 4 / 2 CTAs per SM: cross-CTA overlap of
// gmem staging with mma compute (single-CTA phases can't overlap themselves).
__device__ __forceinline__ unsigned f2tf(float x) {
    unsigned u;
    asm("cvt.rna.tf32.f32 %0, %1;" : "=r"(u) : "f"(x));
    return u;
}

template <int K>
__global__ __launch_bounds__(256) void gemm_tc(
    const float* __restrict__ A, const float* __restrict__ W,
    const float* __restrict__ bias, float* __restrict__ C, int M,
    const int* __restrict__ types, const float* __restrict__ tembed,
    const float* __restrict__ aS, const float* __restrict__ aD)
{
    constexpr int KP = K + 4;
    constexpr int NP = 136;
    extern __shared__ unsigned smem[];
    unsigned* As = smem;                 // [64][KP]
    unsigned* Ws = smem + 64 * KP;       // [K][NP]

    const int tid = threadIdx.x;
    const int lane = tid & 31;
    const int warp = tid >> 5;
    const int mblk = (warp >> 2) * 32;   // 0 or 32
    const int nblk = (warp & 3) * 32;
    const int head = warp & 3;           // warp's 32 cols == one head
    const int row0 = blockIdx.x * 64;
    const int g4 = lane >> 2;
    const int q4 = lane & 3;

    constexpr int K4 = K / 4;
#pragma unroll
    for (int it = 0; it < (64 * K4) / 256; it++) {
        int idx = tid + it * 256;
        int r = idx / K4, c4 = (idx % K4) * 4;
        float4 v = make_float4(0.f, 0.f, 0.f, 0.f);
        if (row0 + r < M) v = *(const float4*)(A + (size_t)(row0 + r) * K + c4);
        uint4 u;
        u.x = f2tf(v.x); u.y = f2tf(v.y); u.z = f2tf(v.z); u.w = f2tf(v.w);
        *(uint4*)(As + r * KP + c4) = u;
    }
#pragma unroll
    for (int it = 0; it < (K * 32) / 256; it++) {
        int idx = tid + it * 256;
        int r = idx >> 5, c4 = (idx & 31) * 4;
        float4 v = *(const float4*)(W + (size_t)r * 128 + c4);
        uint4 u;
        u.x = f2tf(v.x); u.y = f2tf(v.y); u.z = f2tf(v.z); u.w = f2tf(v.w);
        *(uint4*)(Ws + r * NP + c4) = u;
    }
    __syncthreads();

    float acc[2][4][4];
#pragma unroll
    for (int mt = 0; mt < 2; mt++)
#pragma unroll
        for (int nt = 0; nt < 4; nt++)
#pragma unroll
            for (int c = 0; c < 4; c++) acc[mt][nt][c] = 0.f;

#pragma unroll 4
    for (int k0 = 0; k0 < K; k0 += 8) {
        unsigned a[2][4];
#pragma unroll
        for (int mt = 0; mt < 2; mt++) {
            int r = mblk + mt * 16 + g4;
            int c = k0 + q4;
            a[mt][0] = As[r * KP + c];
            a[mt][1] = As[(r + 8) * KP + c];
            a[mt][2] = As[r * KP + c + 4];
            a[mt][3] = As[(r + 8) * KP + c + 4];
        }
#pragma unroll
        for (int nt = 0; nt < 4; nt++) {
            int n = nblk + nt * 8 + g4;
            unsigned b0 = Ws[(k0 + q4) * NP + n];
            unsigned b1 = Ws[(k0 + 4 + q4) * NP + n];
#pragma unroll
            for (int mt = 0; mt < 2; mt++) {
                float* cc = acc[mt][nt];
                asm volatile(
                    "mma.sync.aligned.m16n8k8.row.col.f32.tf32.tf32.f32 "
                    "{%0,%1,%2,%3}, {%4,%5,%6,%7}, {%8,%9}, {%0,%1,%2,%3};"
                    : "+f"(cc[0]), "+f"(cc[1]), "+f"(cc[2]), "+f"(cc[3])
                    : "r"(a[mt][0]), "r"(a[mt][1]), "r"(a[mt][2]), "r"(a[mt][3]),
                      "r"(b0), "r"(b1));
            }
        }
    }

#pragma unroll
    for (int mt = 0; mt < 2; mt++) {
        int rt = row0 + mblk + mt * 16 + g4;
        int rb = rt + 8;
        const float* tet = nullptr;
        const float* teb = nullptr;
        if (types) {
            if (rt < M) tet = tembed + (size_t)types[rt] * 128;
            if (rb < M) teb = tembed + (size_t)types[rb] * 128;
        }
        float es_t = 0.f, ed_t = 0.f, es_b = 0.f, ed_b = 0.f;
#pragma unroll
        for (int nt = 0; nt < 4; nt++) {
            int cbase = nblk + nt * 8 + q4 * 2;
            float b0 = bias[cbase], b1 = bias[cbase + 1];
            float o0 = acc[mt][nt][0] + b0;
            float o1 = acc[mt][nt][1] + b1;
            float o2 = acc[mt][nt][2] + b0;
            float o3 = acc[mt][nt][3] + b1;
            if (tet) { o0 += tet[cbase]; o1 += tet[cbase + 1]; }
            if (teb) { o2 += teb[cbase]; o3 += teb[cbase + 1]; }
            if (rt < M) *(float2*)(C + (size_t)rt * 128 + cbase) = make_float2(o0, o1);
            if (rb < M) *(float2*)(C + (size_t)rb * 128 + cbase) = make_float2(o2, o3);
            if (aS) {
                int hg = head * 32 + nt * 8 + q4 * 2;
                float as0 = aS[hg], as1 = aS[hg + 1];
                float ad0 = aD[hg], ad1 = aD[hg + 1];
                es_t += o0 * as0 + o1 * as1;
                ed_t += o0 * ad0 + o1 * ad1;
                es_b += o2 * as0 + o3 * as1;
                ed_b += o2 * ad0 + o3 * ad1;
            }
        }
        if (aS) {
            es_t += __shfl_xor_sync(0xffffffffu, es_t, 1);
            es_t += __shfl_xor_sync(0xffffffffu, es_t, 2);
            ed_t += __shfl_xor_sync(0xffffffffu, ed_t, 1);
            ed_t += __shfl_xor_sync(0xffffffffu, ed_t, 2);
            es_b += __shfl_xor_sync(0xffffffffu, es_b, 1);
            es_b += __shfl_xor_sync(0xffffffffu, es_b, 2);
            ed_b += __shfl_xor_sync(0xffffffffu, ed_b, 1);
            ed_b += __shfl_xor_sync(0xffffffffu, ed_b, 2);
            if (q4 == 0) {
                if (rt < M) {
                    g_es[(size_t)rt * H_ + head] = es_t;
                    g_ed[(size_t)rt * H_ + head] = ed_t;
                }
                if (rb < M) {
                    g_es[(size_t)rb * H_ + head] = es_b;
                    g_ed[(size_t)rb * H_ + head] = ed_b;
                }
            }
        }
    }
}

// ---------------- GAT aggregation: warp/node, two-pass softmax, no atomics --
// Pass 1: exact segment max, split across the 8 lanes of each head group.
// Pass 2: exp+accumulate, independent iterations -> high MLP.
__global__ __launch_bounds__(256) void agg_kernel(const float* __restrict__ g,
                                                  const float* __restrict__ h_in,
                                                  const float* __restrict__ mask,
                                                  float* __restrict__ h_out) {
    int wid = (blockIdx.x * blockDim.x + threadIdx.x) >> 5;
    int lane = threadIdx.x & 31;
    if (wid >= B_ * N_) return;
    int b = wid / N_, n = wid - b * N_;
    const int* rp = g_rowptr + b * (N_ + 1);
    const int* cs = g_csr + (size_t)b * E_;
    const float* gb = g + (size_t)b * N_ * D_;
    const float* esb = g_es + (size_t)b * N_ * H_;
    int head = lane >> 3;
    int lq = lane & 7;
    float edh = g_ed[(size_t)wid * H_ + head];
    int s0 = rp[n], s1 = rp[n + 1];

    // pass 1: exact max, 8-way parallel within head group
    float m = -1e30f;
    for (int p = s0 + lq; p < s1; p += 8) {
        int src = cs[p];
        float e = esb[src * H_ + head] + edh;
        e = e > 0.f ? e : 0.2f * e;
        m = fmaxf(m, e);
    }
    m = fmaxf(m, __shfl_xor_sync(0xffffffffu, m, 1));
    m = fmaxf(m, __shfl_xor_sync(0xffffffffu, m, 2));
    m = fmaxf(m, __shfl_xor_sync(0xffffffffu, m, 4));

    // pass 2: exp + accumulate (independent iterations)
    float d = 0.f;
    float4 acc = make_float4(0.f, 0.f, 0.f, 0.f);
#pragma unroll 4
    for (int p = s0; p < s1; p++) {
        int src = cs[p];
        float e = esb[src * H_ + head] + edh;
        e = e > 0.f ? e : 0.2f * e;
        float pw = __expf(e - m);
        float4 gv = *(const float4*)(gb + (size_t)src * D_ + lane * 4);
        d += pw;
        acc.x += pw * gv.x;
        acc.y += pw * gv.y;
        acc.z += pw * gv.z;
        acc.w += pw * gv.w;
    }

    float inv = 1.f / (d + 1e-16f);
    float mk = mask[b * N_ + n];
    float4 hv = *(const float4*)(h_in + (size_t)wid * D_ + lane * 4);
    float4 o;
    float v;
    v = acc.x * inv + hv.x; o.x = (v > 0.f ? v : expm1f(v)) * mk;
    v = acc.y * inv + hv.y; o.y = (v > 0.f ? v : expm1f(v)) * mk;
    v = acc.z * inv + hv.z; o.z = (v > 0.f ? v : expm1f(v)) * mk;
    v = acc.w * inv + hv.w; o.w = (v > 0.f ? v : expm1f(v)) * mk;
    *(float4*)(h_out + (size_t)wid * D_ + lane * 4) = o;
}

// ---------------- graph embedding (msum fused) -------------------------------
__global__ void graph_accum_kernel(const float* __restrict__ node_emb,
                                   const float* __restrict__ mask) {
    int b = blockIdx.y;
    int o = threadIdx.x;          // 128
    int n0 = blockIdx.x * 250;
    int n1 = n0 + 250;
    float s = 0.f, sm = 0.f;
    for (int n = n0; n < n1; n++) {
        float mk = mask[b * N_ + n];
        s += node_emb[((size_t)(b * N_ + n)) * D_ + o] * mk;
        sm += mk;
    }
    atomicAdd(&g_gacc[b * D_ + o], s);
    if (o == 0) atomicAdd(&g_msum[b], sm);
}

// reads + restores-to-zero g_gacc/g_msum (512 threads == B_*D_ exactly)
__global__ void finalize_kernel(float* __restrict__ out) {
    int i = blockIdx.x * blockDim.x + threadIdx.x;
    int b = i / D_;
    float ms = g_msum[b];
    ms = ms < 1.f ? 1.f : ms;
    out[(size_t)B_ * N_ * D_ + i] = g_gacc[i] / ms;
    g_gacc[i] = 0.f;
    __syncthreads();                     // all reads of g_msum[b] done
    if ((i & (D_ - 1)) == 0) g_msum[b] = 0.f;
}

// ---------------- launch -----------------------------------------------------
static float* symf(const void* s) { void* p = nullptr; cudaGetSymbolAddress(&p, s); return (float*)p; }

extern "C" void kernel_launch(void* const* d_in, const int* in_sizes, int n_in,
                              void* d_out, int out_size) {
    const float* node_features = (const float*)d_in[0];
    const int*   edge_index    = (const int*)d_in[1];
    const int*   node_types    = (const int*)d_in[2];
    const float* node_mask     = (const float*)d_in[3];
    const float* type_embed    = (const float*)d_in[4];
    const float* in_W          = (const float*)d_in[5];
    const float* in_b          = (const float*)d_in[6];
    const float* gat_W         = (const float*)d_in[7];
    const float* gat_b         = (const float*)d_in[8];
    const float* a_src         = (const float*)d_in[9];
    const float* a_dst         = (const float*)d_in[10];
    const float* out_W         = (const float*)d_in[11];
    const float* out_b         = (const float*)d_in[12];
    float* out = (float*)d_out;

    float* h0   = symf(g_h0);
    float* h1   = symf(g_h1);
    float* gbuf = symf(g_gbuf);

    const int M = B_ * N_;
    const int gemm_grid = (M + 63) / 64;

    const int SMEM64  = (64 * (64 + 4)  + 64  * 136) * 4;   // 52,224
    const int SMEM128 = (64 * (128 + 4) + 128 * 136) * 4;   // 103,424
    cudaFuncSetAttribute(gemm_tc<64>,
                         cudaFuncAttributeMaxDynamicSharedMemorySize, SMEM64);
    cudaFuncSetAttribute(gemm_tc<128>,
                         cudaFuncAttributeMaxDynamicSharedMemorySize, SMEM128);

    // CSR build (dst is layer-invariant -> build once, reuse twice)
    const int e4_grid = (B_ * (E_ / 4) + 255) / 256;
    count_kernel<<<e4_grid, 256>>>(edge_index);
    scan_kernel<<<B_, 1024>>>();
    scatter_kernel<<<e4_grid, 256>>>(edge_index);

    // input projection + type embedding
    gemm_tc<64><<<gemm_grid, 256, SMEM64>>>(node_features, in_W, in_b, h0,
                                            M, node_types, type_embed,
                                            nullptr, nullptr);

    const int warps_grid = (B_ * N_ * 32 + 255) / 256;

    // layer 0 (gemm writes gbuf AND g_es/g_ed)
    gemm_tc<128><<<gemm_grid, 256, SMEM128>>>(h0, gat_W, gat_b, gbuf, M,
                                              nullptr, nullptr, a_src, a_dst);
    agg_kernel<<<warps_grid, 256>>>(gbuf, h0, node_mask, h1);

    // layer 1
    gemm_tc<128><<<gemm_grid, 256, SMEM128>>>(h1, gat_W + D_ * D_, gat_b + D_,
                                              gbuf, M, nullptr, nullptr,
                                              a_src + H_ * (D_ / H_),
                                              a_dst + H_ * (D_ / H_));
    agg_kernel<<<warps_grid, 256>>>(gbuf, h1, node_mask, h0);

    // output projection -> node_emb (directly into d_out)
    gemm_tc<128><<<gemm_grid, 256, SMEM128>>>(h0, out_W, out_b, out, M,
                                              nullptr, nullptr,
                                              nullptr, nullptr);

    // graph embedding
    dim3 gg(40, B_);
    graph_accum_kernel<<<gg, 128>>>(out, node_mask);
    finalize_kernel<<<2, 256>>>(out);
}